// round 1
// baseline (speedup 1.0000x reference)
#include <cuda_runtime.h>
#include <cuda_bf16.h>
#include <math.h>

// ---------------------------------------------------------------------------
// Problem constants
// ---------------------------------------------------------------------------
#define N_CLASS 10000
#define EMB     512
#define HID     1024
#define BATCH   64
#define SEQ     128
#define G4      (4*HID)          // 4096 packed gate columns
#define ROWS    (SEQ*BATCH)      // 8192

// ---------------------------------------------------------------------------
// Device scratch (static allocations; no cudaMalloc allowed)
// ---------------------------------------------------------------------------
__device__ float g_E   [ROWS*EMB];      // embeddings, row r = t*64+b
__device__ float g_XG0 [ROWS*G4];       // layer0 input-side gate preactivations
__device__ float g_H   [ROWS*HID];      // layer0 hidden states, all steps
__device__ float g_XG1 [ROWS*G4];       // layer1 input-side gate preactivations
__device__ float g_Wx0p[EMB*G4];        // packed [k][4u+g]
__device__ float g_Wh0p[HID*G4];
__device__ float g_Wx1p[HID*G4];
__device__ float g_Wh1p[HID*G4];
__device__ float g_b0  [G4];
__device__ float g_b1  [G4];
__device__ float g_c0  [BATCH*HID];
__device__ float g_c1  [BATCH*HID];
__device__ float g_h1a [BATCH*HID];
__device__ float g_h1b [BATCH*HID];
__device__ float g_hz  [BATCH*HID];     // zero initial hidden state

// ---------------------------------------------------------------------------
// Pack 4 gate matrices [K][1024] into interleaved [K][4096]: dst[k][4u+g]
// ---------------------------------------------------------------------------
__global__ void pack_w4(const float* __restrict__ a, const float* __restrict__ b,
                        const float* __restrict__ c, const float* __restrict__ d,
                        float4* __restrict__ dst, int K)
{
    int idx = blockIdx.x * blockDim.x + threadIdx.x;     // over K*1024
    if (idx < K * HID) {
        dst[idx] = make_float4(a[idx], b[idx], c[idx], d[idx]);
    }
}

__global__ void pack_b4(const float* __restrict__ a, const float* __restrict__ b,
                        const float* __restrict__ c, const float* __restrict__ d,
                        float4* __restrict__ dst)
{
    int u = blockIdx.x * blockDim.x + threadIdx.x;
    if (u < HID) dst[u] = make_float4(a[u], b[u], c[u], d[u]);
}

// ---------------------------------------------------------------------------
// Zero the cell states and the zero-h buffer (every launch; out buffers poisoned)
// ---------------------------------------------------------------------------
__global__ void zero_init(float* __restrict__ c0, float* __restrict__ c1,
                          float* __restrict__ hz)
{
    int idx = blockIdx.x * blockDim.x + threadIdx.x;
    if (idx < BATCH * HID) { c0[idx] = 0.f; c1[idx] = 0.f; hz[idx] = 0.f; }
}

// ---------------------------------------------------------------------------
// Embedding gather: E[t*64+b][e] = C[X[b][t]][e]   (float4 granularity)
// ---------------------------------------------------------------------------
__global__ void embed_gather(const int* __restrict__ X,
                             const float4* __restrict__ C4,
                             float4* __restrict__ E4)
{
    int idx = blockIdx.x * blockDim.x + threadIdx.x;     // over 8192*128
    if (idx < ROWS * (EMB/4)) {
        int row = idx >> 7;        // t*64 + b
        int col = idx & 127;
        int t = row >> 6, b = row & 63;
        int tok = X[b * SEQ + t];
        E4[idx] = C4[tok * (EMB/4) + col];
    }
}

// ---------------------------------------------------------------------------
// Generic fp32 SGEMM, row-major: Cmat[M,N] = A[M,K] @ B[K,N] (+bias)
// 64x64 tile, 256 threads, 4x4 per thread, k-tile 16. M%64==0, K%16==0 assumed.
// ---------------------------------------------------------------------------
__global__ __launch_bounds__(256)
void sgemm64(const float* __restrict__ A, const float* __restrict__ B,
             float* __restrict__ Cmat, int M, int N, int K,
             const float* __restrict__ bias)
{
    __shared__ __align__(16) float As[16][68];   // As[k][m]
    __shared__ __align__(16) float Bs[16][68];   // Bs[k][n]

    const int tid = threadIdx.x;
    const int tx = tid & 15;         // -> 4 cols
    const int ty = tid >> 4;         // -> 4 rows
    const int m0 = blockIdx.y * 64;
    const int n0 = blockIdx.x * 64;

    float acc[4][4];
#pragma unroll
    for (int r = 0; r < 4; r++)
#pragma unroll
        for (int c = 0; c < 4; c++) acc[r][c] = 0.f;

    // A-load mapping: one float4 per thread per k-tile
    const int am = tid >> 2;          // 0..63
    const int akg = tid & 3;          // 0..3 (groups of 4 k)
    // B-load mapping: one float4 per thread per k-tile
    const int bk = tid >> 4;          // 0..15
    const int bn4 = tid & 15;         // 0..15 (groups of 4 n)

    for (int k0 = 0; k0 < K; k0 += 16) {
        float4 av = *(const float4*)&A[(size_t)(m0 + am) * K + k0 + akg * 4];
        float4 bv;
        if (n0 + bn4 * 4 < N)
            bv = *(const float4*)&B[(size_t)(k0 + bk) * N + n0 + bn4 * 4];
        else
            bv = make_float4(0.f, 0.f, 0.f, 0.f);

        As[akg * 4 + 0][am] = av.x;
        As[akg * 4 + 1][am] = av.y;
        As[akg * 4 + 2][am] = av.z;
        As[akg * 4 + 3][am] = av.w;
        *(float4*)&Bs[bk][bn4 * 4] = bv;
        __syncthreads();

#pragma unroll
        for (int kk = 0; kk < 16; kk++) {
            float4 a4 = *(const float4*)&As[kk][ty * 4];
            float4 b4 = *(const float4*)&Bs[kk][tx * 4];
            acc[0][0] = fmaf(a4.x, b4.x, acc[0][0]);
            acc[0][1] = fmaf(a4.x, b4.y, acc[0][1]);
            acc[0][2] = fmaf(a4.x, b4.z, acc[0][2]);
            acc[0][3] = fmaf(a4.x, b4.w, acc[0][3]);
            acc[1][0] = fmaf(a4.y, b4.x, acc[1][0]);
            acc[1][1] = fmaf(a4.y, b4.y, acc[1][1]);
            acc[1][2] = fmaf(a4.y, b4.z, acc[1][2]);
            acc[1][3] = fmaf(a4.y, b4.w, acc[1][3]);
            acc[2][0] = fmaf(a4.z, b4.x, acc[2][0]);
            acc[2][1] = fmaf(a4.z, b4.y, acc[2][1]);
            acc[2][2] = fmaf(a4.z, b4.z, acc[2][2]);
            acc[2][3] = fmaf(a4.z, b4.w, acc[2][3]);
            acc[3][0] = fmaf(a4.w, b4.x, acc[3][0]);
            acc[3][1] = fmaf(a4.w, b4.y, acc[3][1]);
            acc[3][2] = fmaf(a4.w, b4.z, acc[3][2]);
            acc[3][3] = fmaf(a4.w, b4.w, acc[3][3]);
        }
        __syncthreads();
    }

#pragma unroll
    for (int r = 0; r < 4; r++) {
        int m = m0 + ty * 4 + r;
#pragma unroll
        for (int c = 0; c < 4; c++) {
            int n = n0 + tx * 4 + c;
            if (n < N) {
                float v = acc[r][c];
                if (bias) v += bias[n];
                Cmat[(size_t)m * N + n] = v;
            }
        }
    }
}

// ---------------------------------------------------------------------------
// Fused LSTM step: gates = xg + h_prev @ Wp + bp ; then c/h pointwise update.
// Gate-interleaved columns: J = 4*u + g, g in {f,i,C,o}.
// Grid: 128 blocks x 256 threads. Block bj owns columns [bj*32, bj*32+32)
// (8 hidden units x 4 gates). Warp w owns rows w*8..w*8+7 (batch).
// ---------------------------------------------------------------------------
__global__ __launch_bounds__(256)
void lstm_step(const float* __restrict__ h_prev,   // [64][1024]
               const float* __restrict__ xg,       // [64][4096] slice for t
               const float* __restrict__ Wp,       // [1024][4096]
               const float* __restrict__ bp,       // [4096]
               float* __restrict__ c,              // [64][1024] in/out
               float* __restrict__ h_out)          // [64][1024]
{
    __shared__ __align__(16) float hs[64][64];     // [m][k] tile of h_prev

    const int tid = threadIdx.x;
    const int tj = tid & 31;              // lane = column within tile
    const int tg = tid >> 5;              // warp id = row group
    const int J  = blockIdx.x * 32 + tj;  // global gate column
    const int m0 = tg * 8;

    float acc[8];
#pragma unroll
    for (int r = 0; r < 8; r++) acc[r] = 0.f;

    for (int k0 = 0; k0 < HID; k0 += 64) {
        __syncthreads();
#pragma unroll
        for (int i = 0; i < 16; i++) {
            int lin = tid + i * 256;
            int m = lin >> 6, k = lin & 63;
            hs[m][k] = h_prev[m * HID + k0 + k];
        }
        __syncthreads();

#pragma unroll 4
        for (int k = 0; k < 64; k += 4) {
            float w0 = Wp[(size_t)(k0 + k + 0) * G4 + J];
            float w1 = Wp[(size_t)(k0 + k + 1) * G4 + J];
            float w2 = Wp[(size_t)(k0 + k + 2) * G4 + J];
            float w3 = Wp[(size_t)(k0 + k + 3) * G4 + J];
#pragma unroll
            for (int r = 0; r < 8; r++) {
                float4 hv = *(const float4*)&hs[m0 + r][k];
                acc[r] = fmaf(hv.x, w0, acc[r]);
                acc[r] = fmaf(hv.y, w1, acc[r]);
                acc[r] = fmaf(hv.z, w2, acc[r]);
                acc[r] = fmaf(hv.w, w3, acc[r]);
            }
        }
    }

    // Pointwise epilogue via warp shuffles (gates of unit u live in lanes
    // base..base+3 of this warp).
    const float bj = bp[J];
    const int g = J & 3;
    const int u = J >> 2;
    const int base = tj & ~3;
    const unsigned mask = 0xFFFFFFFFu;

#pragma unroll
    for (int r = 0; r < 8; r++) {
        int m = m0 + r;
        float a = acc[r] + xg[m * G4 + J] + bj;
        float act = (g == 2) ? tanhf(a) : (1.f / (1.f + expf(-a)));
        float fg = __shfl_sync(mask, act, base + 0);
        float ig = __shfl_sync(mask, act, base + 1);
        float gg = __shfl_sync(mask, act, base + 2);
        float og = __shfl_sync(mask, act, base + 3);
        if (g == 0) {
            float cn = fg * c[m * HID + u] + ig * gg;
            c[m * HID + u] = cn;
            h_out[m * HID + u] = og * tanhf(cn);
        }
    }
}

// ---------------------------------------------------------------------------
// Host launcher (graph-capturable: kernel launches only)
// ---------------------------------------------------------------------------
extern "C" void kernel_launch(void* const* d_in, const int* in_sizes, int n_in,
                              void* d_out, int out_size)
{
    const int*   X     = (const int*)  d_in[0];
    const float* Cemb  = (const float*)d_in[1];
    const float* W_fx  = (const float*)d_in[2];
    const float* W_fh  = (const float*)d_in[3];
    const float* W_ix  = (const float*)d_in[4];
    const float* W_ih  = (const float*)d_in[5];
    const float* W_Cx  = (const float*)d_in[6];
    const float* W_Ch  = (const float*)d_in[7];
    const float* W_ox  = (const float*)d_in[8];
    const float* W_oh  = (const float*)d_in[9];
    const float* W_fx1 = (const float*)d_in[10];
    const float* W_fh1 = (const float*)d_in[11];
    const float* W_ix1 = (const float*)d_in[12];
    const float* W_ih1 = (const float*)d_in[13];   // unused by reference recurrence (bug kept)
    const float* W_Cx1 = (const float*)d_in[14];
    const float* W_Ch1 = (const float*)d_in[15];
    const float* W_ox1 = (const float*)d_in[16];
    const float* W_oh1 = (const float*)d_in[17];
    const float* W_out = (const float*)d_in[18];
    const float* b_f   = (const float*)d_in[19];
    const float* b_i   = (const float*)d_in[20];
    const float* b_C   = (const float*)d_in[21];
    const float* b_o   = (const float*)d_in[22];
    const float* b_f1  = (const float*)d_in[23];
    const float* b_i1  = (const float*)d_in[24];
    const float* b_C1  = (const float*)d_in[25];
    const float* b_o1  = (const float*)d_in[26];
    const float* b_out = (const float*)d_in[27];
    float* out = (float*)d_out;
    (void)W_ih1; (void)n_in; (void)in_sizes; (void)out_size;

    float *E, *XG0, *H, *XG1, *Wx0p, *Wh0p, *Wx1p, *Wh1p, *b0, *b1;
    float *c0, *c1, *h1a, *h1b, *hz;
    cudaGetSymbolAddress((void**)&E,    g_E);
    cudaGetSymbolAddress((void**)&XG0,  g_XG0);
    cudaGetSymbolAddress((void**)&H,    g_H);
    cudaGetSymbolAddress((void**)&XG1,  g_XG1);
    cudaGetSymbolAddress((void**)&Wx0p, g_Wx0p);
    cudaGetSymbolAddress((void**)&Wh0p, g_Wh0p);
    cudaGetSymbolAddress((void**)&Wx1p, g_Wx1p);
    cudaGetSymbolAddress((void**)&Wh1p, g_Wh1p);
    cudaGetSymbolAddress((void**)&b0,   g_b0);
    cudaGetSymbolAddress((void**)&b1,   g_b1);
    cudaGetSymbolAddress((void**)&c0,   g_c0);
    cudaGetSymbolAddress((void**)&c1,   g_c1);
    cudaGetSymbolAddress((void**)&h1a,  g_h1a);
    cudaGetSymbolAddress((void**)&h1b,  g_h1b);
    cudaGetSymbolAddress((void**)&hz,   g_hz);

    // Pack weights (gate-interleaved) and biases
    pack_w4<<<(EMB*HID + 255)/256, 256>>>(W_fx, W_ix, W_Cx, W_ox, (float4*)Wx0p, EMB);
    pack_w4<<<(HID*HID + 255)/256, 256>>>(W_fh, W_ih, W_Ch, W_oh, (float4*)Wh0p, HID);
    pack_w4<<<(HID*HID + 255)/256, 256>>>(W_fx1, W_ix1, W_Cx1, W_ox1, (float4*)Wx1p, HID);
    // NOTE: reference layer-1 i-gate recurrence uses layer-0 W_ih (kept on purpose)
    pack_w4<<<(HID*HID + 255)/256, 256>>>(W_fh1, W_ih, W_Ch1, W_oh1, (float4*)Wh1p, HID);
    pack_b4<<<(HID + 255)/256, 256>>>(b_f,  b_i,  b_C,  b_o,  (float4*)b0);
    pack_b4<<<(HID + 255)/256, 256>>>(b_f1, b_i1, b_C1, b_o1, (float4*)b1);

    // Zero cell states and zero-h
    zero_init<<<(BATCH*HID + 255)/256, 256>>>(c0, c1, hz);

    // Embedding gather
    embed_gather<<<(ROWS*(EMB/4) + 255)/256, 256>>>(X, (const float4*)Cemb, (float4*)E);

    // Layer 0 input-side projections: XG0 = E @ Wx0p   [8192,512]x[512,4096]
    sgemm64<<<dim3(G4/64, ROWS/64), 256>>>(E, Wx0p, XG0, ROWS, G4, EMB, nullptr);

    // Layer 0 recurrence
    for (int t = 0; t < SEQ; t++) {
        const float* hp = (t == 0) ? hz : (H + (size_t)(t - 1) * BATCH * HID);
        lstm_step<<<128, 256>>>(hp, XG0 + (size_t)t * BATCH * G4, Wh0p, b0,
                                c0, H + (size_t)t * BATCH * HID);
    }

    // Layer 1 input-side projections: XG1 = H @ Wx1p   [8192,1024]x[1024,4096]
    sgemm64<<<dim3(G4/64, ROWS/64), 256>>>(H, Wx1p, XG1, ROWS, G4, HID, nullptr);

    // Layer 1 recurrence (ping-pong h buffers)
    const float* hp = hz;
    float* ho = h1a;
    for (int t = 0; t < SEQ; t++) {
        ho = (t & 1) ? h1b : h1a;
        lstm_step<<<128, 256>>>(hp, XG1 + (size_t)t * BATCH * G4, Wh1p, b1,
                                c1, ho);
        hp = ho;
    }

    // Output projection: out = h1 @ W_out + b_out   [64,1024]x[1024,10000]
    sgemm64<<<dim3((N_CLASS + 63)/64, BATCH/64), 256>>>(hp, W_out, out,
                                                        BATCH, N_CLASS, HID, b_out);
}

// round 3
// speedup vs baseline: 1.6784x; 1.6784x over previous
#include <cuda_runtime.h>
#include <cuda_bf16.h>
#include <cstdint>
#include <math.h>

// ---------------------------------------------------------------------------
// Problem constants
// ---------------------------------------------------------------------------
#define N_CLASS 10000
#define EMB     512
#define HID     1024
#define BATCH   64
#define SEQ     128
#define G4      (4*HID)          // 4096 gate columns (interleaved J = 4u+g)
#define ROWS    (SEQ*BATCH)      // 8192

// ---------------------------------------------------------------------------
// mma.sync / ldmatrix helpers (arch-portable sm_80+ path; tcgen05 not
// available: harness compiles for plain sm_103 target)
// ---------------------------------------------------------------------------
__device__ __forceinline__ uint32_t smem_u32(const void* p) {
    uint32_t a;
    asm("{ .reg .u64 t; cvta.to.shared.u64 t, %1; cvt.u32.u64 %0, t; }"
        : "=r"(a) : "l"(p));
    return a;
}

__device__ __forceinline__ void ldmatrix_x4(uint32_t* r, uint32_t addr) {
    asm volatile("ldmatrix.sync.aligned.m8n8.x4.shared.b16 {%0,%1,%2,%3}, [%4];"
                 : "=r"(r[0]), "=r"(r[1]), "=r"(r[2]), "=r"(r[3]) : "r"(addr));
}

// D(f32) += A(bf16) * B(bf16), m16n8k16, A row-major, B col-major
__device__ __forceinline__ void mma16816(float* d, const uint32_t* a,
                                         const uint32_t* b) {
    asm volatile(
        "mma.sync.aligned.m16n8k16.row.col.f32.bf16.bf16.f32 "
        "{%0,%1,%2,%3}, {%4,%5,%6,%7}, {%8,%9}, {%0,%1,%2,%3};"
        : "+f"(d[0]), "+f"(d[1]), "+f"(d[2]), "+f"(d[3])
        : "r"(a[0]), "r"(a[1]), "r"(a[2]), "r"(a[3]),
          "r"(b[0]), "r"(b[1]));
}

__device__ __forceinline__ float sigf(float x) { return 1.f / (1.f + expf(-x)); }

// ---------------------------------------------------------------------------
// Device scratch (static; no cudaMalloc allowed)
// ---------------------------------------------------------------------------
__device__ __nv_bfloat16 g_Ehi [ROWS*EMB];     // embeddings split bf16, row=t*64+b
__device__ __nv_bfloat16 g_Elo [ROWS*EMB];
__device__ __nv_bfloat16 g_Hhi [ROWS*HID];     // layer0 h, row=t*64+m, col=u
__device__ __nv_bfloat16 g_Hlo [ROWS*HID];
__device__ __nv_bfloat16 g_B0hi[G4*EMB];       // input weights L0, [J=4u+g][k]
__device__ __nv_bfloat16 g_B0lo[G4*EMB];
__device__ __nv_bfloat16 g_B1hi[G4*HID];       // input weights L1
__device__ __nv_bfloat16 g_B1lo[G4*HID];
__device__ __nv_bfloat16 g_R0hi[G4*HID];       // recurrent weights L0, [J][k]
__device__ __nv_bfloat16 g_R0lo[G4*HID];
__device__ __nv_bfloat16 g_R1hi[G4*HID];       // recurrent weights L1
__device__ __nv_bfloat16 g_R1lo[G4*HID];
__device__ float g_XG0[ROWS*G4];               // gate preacts (interleaved cols)
__device__ float g_XG1[ROWS*G4];
__device__ float g_b0 [G4];
__device__ float g_b1 [G4];
__device__ float g_c0 [BATCH*HID];             // [m][u]
__device__ float g_c1 [BATCH*HID];
__device__ __nv_bfloat16 g_h1ah[BATCH*HID];    // layer1 h ping-pong, split bf16
__device__ __nv_bfloat16 g_h1al[BATCH*HID];
__device__ __nv_bfloat16 g_h1bh[BATCH*HID];
__device__ __nv_bfloat16 g_h1bl[BATCH*HID];
__device__ __nv_bfloat16 g_hzh [BATCH*HID];    // zero h (hi)
__device__ __nv_bfloat16 g_hzl [BATCH*HID];    // zero h (lo)
__device__ float g_h1f [BATCH*HID];            // layer1 h fp32 (for out proj)

// ---------------------------------------------------------------------------
// Prep kernels
// ---------------------------------------------------------------------------
// W[K][1024](fp32, col u) -> B[4u+g][K] split bf16 (transpose + interleave)
__global__ void wcvt(const float* __restrict__ W, __nv_bfloat16* __restrict__ Bh,
                     __nv_bfloat16* __restrict__ Bl, int K, int g)
{
    __shared__ float s[32][33];
    int k0 = blockIdx.x * 32, u0 = blockIdx.y * 32;
    int tx = threadIdx.x, ty = threadIdx.y;          // (32, 8)
#pragma unroll
    for (int j = 0; j < 4; j++)
        s[ty + j*8][tx] = W[(size_t)(k0 + ty + j*8) * HID + u0 + tx];
    __syncthreads();
#pragma unroll
    for (int j = 0; j < 4; j++) {
        int uu = ty + j*8;
        float v = s[tx][uu];
        __nv_bfloat16 hi = __float2bfloat16(v);
        size_t o = (size_t)(4*(u0 + uu) + g) * K + k0 + tx;
        Bh[o] = hi;
        Bl[o] = __float2bfloat16(v - __bfloat162float(hi));
    }
}

__global__ void pack_b4(const float* __restrict__ a, const float* __restrict__ b,
                        const float* __restrict__ c, const float* __restrict__ d,
                        float4* __restrict__ dst)
{
    int u = blockIdx.x * blockDim.x + threadIdx.x;
    if (u < HID) dst[u] = make_float4(a[u], b[u], c[u], d[u]);  // [4u+g]
}

__global__ void zero_init(float* __restrict__ c0, float* __restrict__ c1,
                          __nv_bfloat16* __restrict__ hzh,
                          __nv_bfloat16* __restrict__ hzl)
{
    int idx = blockIdx.x * blockDim.x + threadIdx.x;
    if (idx < BATCH * HID) {
        c0[idx] = 0.f; c1[idx] = 0.f;
        hzh[idx] = __float2bfloat16(0.f);
        hzl[idx] = __float2bfloat16(0.f);
    }
}

__global__ void embed_bf16(const int* __restrict__ X, const float* __restrict__ C,
                           __nv_bfloat16* __restrict__ Eh, __nv_bfloat16* __restrict__ El)
{
    int idx = blockIdx.x * blockDim.x + threadIdx.x;
    if (idx < ROWS * EMB) {
        int row = idx >> 9, e = idx & 511;
        int t = row >> 6, b = row & 63;
        int tok = X[b * SEQ + t];
        float v = C[(size_t)tok * EMB + e];
        __nv_bfloat16 hi = __float2bfloat16(v);
        Eh[idx] = hi;
        El[idx] = __float2bfloat16(v - __bfloat162float(hi));
    }
}

// ---------------------------------------------------------------------------
// HMMA split-bf16 GEMM: C[M][4096] = A[M][K] @ B[4096][K]^T  (fp32 out)
// Block: 128m x 64n, 256 thr (8 warps: 4 m-warps x 2 n-warps), k-chunk 32.
// Smem rows padded to 80B (conflict-free ldmatrix + LDS patterns).
// ---------------------------------------------------------------------------
__global__ __launch_bounds__(256)
void mm_mma(const __nv_bfloat16* __restrict__ Ah, const __nv_bfloat16* __restrict__ Al,
            const __nv_bfloat16* __restrict__ Bh, const __nv_bfloat16* __restrict__ Bl,
            float* __restrict__ Cm, int K)
{
    __shared__ __align__(16) char sA[2][128*80];
    __shared__ __align__(16) char sB[2][64*80];

    const int tid = threadIdx.x, lane = tid & 31, w = tid >> 5;
    const int m0 = blockIdx.y * 128, n0 = blockIdx.x * 64;
    const int wm = (w & 3) * 32, wn = (w >> 2) * 32;
    const int g = lane >> 2, tig = lane & 3;
    const int sub = lane >> 3, lr = lane & 7;

    float acc[2][4][4];
#pragma unroll
    for (int ti = 0; ti < 2; ti++)
#pragma unroll
        for (int j = 0; j < 4; j++)
#pragma unroll
            for (int q = 0; q < 4; q++) acc[ti][j][q] = 0.f;

    uint32_t aBase[2][2];   // [hi/lo][mtile]
#pragma unroll
    for (int hl = 0; hl < 2; hl++)
#pragma unroll
        for (int ti = 0; ti < 2; ti++)
            aBase[hl][ti] = smem_u32(sA) + hl*(128*80)
                          + (wm + ti*16 + (sub & 1)*8 + lr)*80 + (sub >> 1)*16;

    const int nchunk = K >> 5;
    for (int c = 0; c < nchunk; c++) {
        __syncthreads();
        const int kb = c * 32;
        // A: 128 rows x 4 segs(16B) per matrix -> 512 uint4; 2 iters
#pragma unroll
        for (int i = 0; i < 2; i++) {
            int lin = tid + i * 256;
            int r = lin >> 2, s = lin & 3;
            size_t go = (size_t)(m0 + r) * K + kb + s * 8;
            *(uint4*)(sA[0] + r*80 + s*16) = *(const uint4*)(Ah + go);
            *(uint4*)(sA[1] + r*80 + s*16) = *(const uint4*)(Al + go);
        }
        // B: 64 rows x 4 segs per matrix -> 256 uint4; 1 iter
        {
            int r = tid >> 2, s = tid & 3;
            size_t go = (size_t)(n0 + r) * K + kb + s * 8;
            *(uint4*)(sB[0] + r*80 + s*16) = *(const uint4*)(Bh + go);
            *(uint4*)(sB[1] + r*80 + s*16) = *(const uint4*)(Bl + go);
        }
        __syncthreads();

#pragma unroll
        for (int ks = 0; ks < 2; ks++) {
            uint32_t a[2][2][4];
#pragma unroll
            for (int hl = 0; hl < 2; hl++)
#pragma unroll
                for (int ti = 0; ti < 2; ti++)
                    ldmatrix_x4(a[hl][ti], aBase[hl][ti] + ks*32);
            uint32_t bh[4][2], bl[4][2];
#pragma unroll
            for (int j = 0; j < 4; j++) {
                int off = (wn + 8*j + g)*80 + ks*32 + tig*4;
                bh[j][0] = *(const uint32_t*)(sB[0] + off);
                bh[j][1] = *(const uint32_t*)(sB[0] + off + 16);
                bl[j][0] = *(const uint32_t*)(sB[1] + off);
                bl[j][1] = *(const uint32_t*)(sB[1] + off + 16);
            }
#pragma unroll
            for (int ti = 0; ti < 2; ti++)
#pragma unroll
                for (int j = 0; j < 4; j++) {
                    mma16816(acc[ti][j], a[0][ti], bh[j]);
                    mma16816(acc[ti][j], a[0][ti], bl[j]);
                    mma16816(acc[ti][j], a[1][ti], bh[j]);
                }
        }
    }

#pragma unroll
    for (int ti = 0; ti < 2; ti++) {
        int row = m0 + wm + ti*16 + g;
#pragma unroll
        for (int j = 0; j < 4; j++) {
            int col = n0 + wn + 8*j + tig*2;
            *(float2*)&Cm[(size_t)row * G4 + col] =
                make_float2(acc[ti][j][0], acc[ti][j][1]);
            *(float2*)&Cm[(size_t)(row + 8) * G4 + col] =
                make_float2(acc[ti][j][2], acc[ti][j][3]);
        }
    }
}

// ---------------------------------------------------------------------------
// Fused HMMA LSTM step.
// gates[64][4096] = hprev[64][1024] @ W[4096][1024]^T + xg + bias; pointwise.
// 128 blocks x 128 thr (4 warps). Warp w: rows 16w..16w+15; n-tile = 32 cols.
// h written out as split bf16 [m][u] (A layout for next step / XG1 GEMM).
// ---------------------------------------------------------------------------
__global__ __launch_bounds__(128)
void lstm_step(const __nv_bfloat16* __restrict__ hph, const __nv_bfloat16* __restrict__ hpl,
               const __nv_bfloat16* __restrict__ Wh,  const __nv_bfloat16* __restrict__ Wl,
               const float* __restrict__ xg,          // [64][4096] for this t
               const float* __restrict__ bias,        // [4096]
               float* __restrict__ cbuf,              // [64][1024]
               __nv_bfloat16* __restrict__ hoh, __nv_bfloat16* __restrict__ hol,
               float* __restrict__ hof)               // fp32 h out or nullptr
{
    __shared__ __align__(16) char sA[2][64*80];
    __shared__ __align__(16) char sB[2][32*80];

    const int tid = threadIdx.x, lane = tid & 31, w = tid >> 5;
    const int n0 = blockIdx.x * 32;
    const int g = lane >> 2, tig = lane & 3;
    const int sub = lane >> 3, lr = lane & 7;

    float acc[4][4];
#pragma unroll
    for (int j = 0; j < 4; j++)
#pragma unroll
        for (int q = 0; q < 4; q++) acc[j][q] = 0.f;

    uint32_t aBase[2];
#pragma unroll
    for (int hl = 0; hl < 2; hl++)
        aBase[hl] = smem_u32(sA) + hl*(64*80)
                  + (16*w + (sub & 1)*8 + lr)*80 + (sub >> 1)*16;

    for (int c = 0; c < 32; c++) {
        __syncthreads();
        const int kb = c * 32;
        // A: 64 rows x 4 segs x2 -> per matrix 256 uint4; 2 iters
#pragma unroll
        for (int i = 0; i < 2; i++) {
            int lin = tid + i * 128;
            int r = lin >> 2, s = lin & 3;
            size_t go = (size_t)r * HID + kb + s * 8;
            *(uint4*)(sA[0] + r*80 + s*16) = *(const uint4*)(hph + go);
            *(uint4*)(sA[1] + r*80 + s*16) = *(const uint4*)(hpl + go);
        }
        // B: 32 rows x 4 segs -> 128 uint4 per matrix; 1 iter
        {
            int r = tid >> 2, s = tid & 3;
            size_t go = (size_t)(n0 + r) * HID + kb + s * 8;
            *(uint4*)(sB[0] + r*80 + s*16) = *(const uint4*)(Wh + go);
            *(uint4*)(sB[1] + r*80 + s*16) = *(const uint4*)(Wl + go);
        }
        __syncthreads();

#pragma unroll
        for (int ks = 0; ks < 2; ks++) {
            uint32_t a[2][4];
            ldmatrix_x4(a[0], aBase[0] + ks*32);
            ldmatrix_x4(a[1], aBase[1] + ks*32);
            uint32_t bh[4][2], bl[4][2];
#pragma unroll
            for (int j = 0; j < 4; j++) {
                int off = (8*j + g)*80 + ks*32 + tig*4;
                bh[j][0] = *(const uint32_t*)(sB[0] + off);
                bh[j][1] = *(const uint32_t*)(sB[0] + off + 16);
                bl[j][0] = *(const uint32_t*)(sB[1] + off);
                bl[j][1] = *(const uint32_t*)(sB[1] + off + 16);
            }
#pragma unroll
            for (int j = 0; j < 4; j++) {
                mma16816(acc[j], a[0], bh[j]);
                mma16816(acc[j], a[0], bl[j]);
                mma16816(acc[j], a[1], bh[j]);
            }
        }
    }

    // Pointwise epilogue. Even tig lanes hold (f,i) cols, odd (C,o) of same u.
    const int m1 = 16*w + g;
    const int m2 = m1 + 8;
    const bool co = (tig & 1);
#pragma unroll
    for (int j = 0; j < 4; j++) {
        int J = n0 + 8*j + tig*2;
        float2 bb = *(const float2*)&bias[J];
        float2 x1 = *(const float2*)&xg[m1*G4 + J];
        float2 x2 = *(const float2*)&xg[m2*G4 + J];
        float p0 = acc[j][0] + x1.x + bb.x;
        float p1 = acc[j][1] + x1.y + bb.y;
        float p2 = acc[j][2] + x2.x + bb.x;
        float p3 = acc[j][3] + x2.y + bb.y;
        float a0 = co ? tanhf(p0) : sigf(p0);
        float a1 = sigf(p1);
        float a2 = co ? tanhf(p2) : sigf(p2);
        float a3 = sigf(p3);
        float C1 = __shfl_xor_sync(0xFFFFFFFFu, a0, 1);
        float O1 = __shfl_xor_sync(0xFFFFFFFFu, a1, 1);
        float C2 = __shfl_xor_sync(0xFFFFFFFFu, a2, 1);
        float O2 = __shfl_xor_sync(0xFFFFFFFFu, a3, 1);
        if (!co) {
            int u = J >> 2;
            float cn1 = a0 * cbuf[m1*HID + u] + a1 * C1;
            cbuf[m1*HID + u] = cn1;
            float h1 = O1 * tanhf(cn1);
            __nv_bfloat16 hh = __float2bfloat16(h1);
            hoh[m1*HID + u] = hh;
            hol[m1*HID + u] = __float2bfloat16(h1 - __bfloat162float(hh));
            if (hof) hof[m1*HID + u] = h1;

            float cn2 = a2 * cbuf[m2*HID + u] + a3 * C2;
            cbuf[m2*HID + u] = cn2;
            float h2 = O2 * tanhf(cn2);
            hh = __float2bfloat16(h2);
            hoh[m2*HID + u] = hh;
            hol[m2*HID + u] = __float2bfloat16(h2 - __bfloat162float(hh));
            if (hof) hof[m2*HID + u] = h2;
        }
    }
}

// ---------------------------------------------------------------------------
// Output projection: out[64][N] = A[64][K] @ B[K][N] + bias (fp32, small)
// ---------------------------------------------------------------------------
__global__ __launch_bounds__(256)
void sgemm_out(const float* __restrict__ A, const float* __restrict__ B,
               float* __restrict__ Cmat, int N, int K, const float* __restrict__ bias)
{
    __shared__ __align__(16) float As[16][68];
    __shared__ __align__(16) float Bs[16][68];

    const int tid = threadIdx.x;
    const int tx = tid & 15, ty = tid >> 4;
    const int n0 = blockIdx.x * 64;

    float acc[4][4];
#pragma unroll
    for (int r = 0; r < 4; r++)
#pragma unroll
        for (int c = 0; c < 4; c++) acc[r][c] = 0.f;

    const int am = tid >> 2;          // 0..63
    const int akg = tid & 3;
    const int bk = tid >> 4;
    const int bn4 = tid & 15;

    for (int k0 = 0; k0 < K; k0 += 16) {
        float4 av = *(const float4*)&A[(size_t)am * K + k0 + akg * 4];
        float4 bv;
        if (n0 + bn4 * 4 < N)
            bv = *(const float4*)&B[(size_t)(k0 + bk) * N + n0 + bn4 * 4];
        else
            bv = make_float4(0.f, 0.f, 0.f, 0.f);
        As[akg*4 + 0][am] = av.x;
        As[akg*4 + 1][am] = av.y;
        As[akg*4 + 2][am] = av.z;
        As[akg*4 + 3][am] = av.w;
        *(float4*)&Bs[bk][bn4 * 4] = bv;
        __syncthreads();
#pragma unroll
        for (int kk = 0; kk < 16; kk++) {
            float4 a4 = *(const float4*)&As[kk][ty * 4];
            float4 b4 = *(const float4*)&Bs[kk][tx * 4];
            acc[0][0] = fmaf(a4.x, b4.x, acc[0][0]);
            acc[0][1] = fmaf(a4.x, b4.y, acc[0][1]);
            acc[0][2] = fmaf(a4.x, b4.z, acc[0][2]);
            acc[0][3] = fmaf(a4.x, b4.w, acc[0][3]);
            acc[1][0] = fmaf(a4.y, b4.x, acc[1][0]);
            acc[1][1] = fmaf(a4.y, b4.y, acc[1][1]);
            acc[1][2] = fmaf(a4.y, b4.z, acc[1][2]);
            acc[1][3] = fmaf(a4.y, b4.w, acc[1][3]);
            acc[2][0] = fmaf(a4.z, b4.x, acc[2][0]);
            acc[2][1] = fmaf(a4.z, b4.y, acc[2][1]);
            acc[2][2] = fmaf(a4.z, b4.z, acc[2][2]);
            acc[2][3] = fmaf(a4.z, b4.w, acc[2][3]);
            acc[3][0] = fmaf(a4.w, b4.x, acc[3][0]);
            acc[3][1] = fmaf(a4.w, b4.y, acc[3][1]);
            acc[3][2] = fmaf(a4.w, b4.z, acc[3][2]);
            acc[3][3] = fmaf(a4.w, b4.w, acc[3][3]);
        }
        __syncthreads();
    }

#pragma unroll
    for (int r = 0; r < 4; r++) {
        int m = ty * 4 + r;
#pragma unroll
        for (int c = 0; c < 4; c++) {
            int n = n0 + tx * 4 + c;
            if (n < N) Cmat[(size_t)m * N + n] = acc[r][c] + bias[n];
        }
    }
}

// ---------------------------------------------------------------------------
// Host launcher (graph-capturable: kernel launches only)
// ---------------------------------------------------------------------------
extern "C" void kernel_launch(void* const* d_in, const int* in_sizes, int n_in,
                              void* d_out, int out_size)
{
    const int*   X     = (const int*)  d_in[0];
    const float* Cemb  = (const float*)d_in[1];
    const float* W_fx  = (const float*)d_in[2];
    const float* W_fh  = (const float*)d_in[3];
    const float* W_ix  = (const float*)d_in[4];
    const float* W_ih  = (const float*)d_in[5];
    const float* W_Cx  = (const float*)d_in[6];
    const float* W_Ch  = (const float*)d_in[7];
    const float* W_ox  = (const float*)d_in[8];
    const float* W_oh  = (const float*)d_in[9];
    const float* W_fx1 = (const float*)d_in[10];
    const float* W_fh1 = (const float*)d_in[11];
    const float* W_ix1 = (const float*)d_in[12];
    const float* W_ih1 = (const float*)d_in[13];   // unused (reference bug kept)
    const float* W_Cx1 = (const float*)d_in[14];
    const float* W_Ch1 = (const float*)d_in[15];
    const float* W_ox1 = (const float*)d_in[16];
    const float* W_oh1 = (const float*)d_in[17];
    const float* W_out = (const float*)d_in[18];
    const float* b_f   = (const float*)d_in[19];
    const float* b_i   = (const float*)d_in[20];
    const float* b_C   = (const float*)d_in[21];
    const float* b_o   = (const float*)d_in[22];
    const float* b_f1  = (const float*)d_in[23];
    const float* b_i1  = (const float*)d_in[24];
    const float* b_C1  = (const float*)d_in[25];
    const float* b_o1  = (const float*)d_in[26];
    const float* b_out = (const float*)d_in[27];
    float* out = (float*)d_out;
    (void)W_ih1; (void)n_in; (void)in_sizes; (void)out_size;

    __nv_bfloat16 *Ehi, *Elo, *Hhi, *Hlo, *B0h, *B0l, *B1h, *B1l;
    __nv_bfloat16 *R0h, *R0l, *R1h, *R1l;
    __nv_bfloat16 *h1ah, *h1al, *h1bh, *h1bl, *hzh, *hzl;
    float *XG0, *XG1, *b0, *b1, *c0, *c1, *h1f;
    cudaGetSymbolAddress((void**)&Ehi, g_Ehi);   cudaGetSymbolAddress((void**)&Elo, g_Elo);
    cudaGetSymbolAddress((void**)&Hhi, g_Hhi);   cudaGetSymbolAddress((void**)&Hlo, g_Hlo);
    cudaGetSymbolAddress((void**)&B0h, g_B0hi);  cudaGetSymbolAddress((void**)&B0l, g_B0lo);
    cudaGetSymbolAddress((void**)&B1h, g_B1hi);  cudaGetSymbolAddress((void**)&B1l, g_B1lo);
    cudaGetSymbolAddress((void**)&R0h, g_R0hi);  cudaGetSymbolAddress((void**)&R0l, g_R0lo);
    cudaGetSymbolAddress((void**)&R1h, g_R1hi);  cudaGetSymbolAddress((void**)&R1l, g_R1lo);
    cudaGetSymbolAddress((void**)&XG0, g_XG0);   cudaGetSymbolAddress((void**)&XG1, g_XG1);
    cudaGetSymbolAddress((void**)&b0, g_b0);     cudaGetSymbolAddress((void**)&b1, g_b1);
    cudaGetSymbolAddress((void**)&c0, g_c0);     cudaGetSymbolAddress((void**)&c1, g_c1);
    cudaGetSymbolAddress((void**)&h1ah, g_h1ah); cudaGetSymbolAddress((void**)&h1al, g_h1al);
    cudaGetSymbolAddress((void**)&h1bh, g_h1bh); cudaGetSymbolAddress((void**)&h1bl, g_h1bl);
    cudaGetSymbolAddress((void**)&hzh, g_hzh);   cudaGetSymbolAddress((void**)&hzl, g_hzl);
    cudaGetSymbolAddress((void**)&h1f, g_h1f);

    dim3 tb(32, 8);
    // Input-side weights: B[J=4u+g][k]
    wcvt<<<dim3(EMB/32, HID/32), tb>>>(W_fx,  B0h, B0l, EMB, 0);
    wcvt<<<dim3(EMB/32, HID/32), tb>>>(W_ix,  B0h, B0l, EMB, 1);
    wcvt<<<dim3(EMB/32, HID/32), tb>>>(W_Cx,  B0h, B0l, EMB, 2);
    wcvt<<<dim3(EMB/32, HID/32), tb>>>(W_ox,  B0h, B0l, EMB, 3);
    wcvt<<<dim3(HID/32, HID/32), tb>>>(W_fx1, B1h, B1l, HID, 0);
    wcvt<<<dim3(HID/32, HID/32), tb>>>(W_ix1, B1h, B1l, HID, 1);
    wcvt<<<dim3(HID/32, HID/32), tb>>>(W_Cx1, B1h, B1l, HID, 2);
    wcvt<<<dim3(HID/32, HID/32), tb>>>(W_ox1, B1h, B1l, HID, 3);
    // Recurrent weights (layer1 i-gate reuses layer0 W_ih — reference bug kept)
    wcvt<<<dim3(HID/32, HID/32), tb>>>(W_fh,  R0h, R0l, HID, 0);
    wcvt<<<dim3(HID/32, HID/32), tb>>>(W_ih,  R0h, R0l, HID, 1);
    wcvt<<<dim3(HID/32, HID/32), tb>>>(W_Ch,  R0h, R0l, HID, 2);
    wcvt<<<dim3(HID/32, HID/32), tb>>>(W_oh,  R0h, R0l, HID, 3);
    wcvt<<<dim3(HID/32, HID/32), tb>>>(W_fh1, R1h, R1l, HID, 0);
    wcvt<<<dim3(HID/32, HID/32), tb>>>(W_ih,  R1h, R1l, HID, 1);
    wcvt<<<dim3(HID/32, HID/32), tb>>>(W_Ch1, R1h, R1l, HID, 2);
    wcvt<<<dim3(HID/32, HID/32), tb>>>(W_oh1, R1h, R1l, HID, 3);
    pack_b4<<<(HID + 255)/256, 256>>>(b_f,  b_i,  b_C,  b_o,  (float4*)b0);
    pack_b4<<<(HID + 255)/256, 256>>>(b_f1, b_i1, b_C1, b_o1, (float4*)b1);

    zero_init<<<(BATCH*HID + 255)/256, 256>>>(c0, c1, hzh, hzl);
    embed_bf16<<<(ROWS*EMB + 255)/256, 256>>>(X, Cemb, Ehi, Elo);

    // XG0 = E @ Wx0 (HMMA)
    mm_mma<<<dim3(G4/64, ROWS/128), 256>>>(Ehi, Elo, B0h, B0l, XG0, EMB);

    // Layer 0 recurrence (h written directly as split bf16 rows t*64..)
    for (int t = 0; t < SEQ; t++) {
        const __nv_bfloat16* hh = (t == 0) ? hzh : (Hhi + (size_t)(t-1)*BATCH*HID);
        const __nv_bfloat16* hl = (t == 0) ? hzl : (Hlo + (size_t)(t-1)*BATCH*HID);
        lstm_step<<<128, 128>>>(hh, hl, R0h, R0l,
                                XG0 + (size_t)t*BATCH*G4, b0, c0,
                                Hhi + (size_t)t*BATCH*HID,
                                Hlo + (size_t)t*BATCH*HID, nullptr);
    }

    // XG1 = H @ Wx1 (HMMA)
    mm_mma<<<dim3(G4/64, ROWS/128), 256>>>(Hhi, Hlo, B1h, B1l, XG1, HID);

    // Layer 1 recurrence (ping-pong split-bf16 h; fp32 h kept for out proj)
    const __nv_bfloat16* hh = hzh;
    const __nv_bfloat16* hl = hzl;
    for (int t = 0; t < SEQ; t++) {
        __nv_bfloat16* oh = (t & 1) ? h1bh : h1ah;
        __nv_bfloat16* ol = (t & 1) ? h1bl : h1al;
        lstm_step<<<128, 128>>>(hh, hl, R1h, R1l,
                                XG1 + (size_t)t*BATCH*G4, b1, c1,
                                oh, ol, h1f);
        hh = oh; hl = ol;
    }

    // out = h1 @ W_out + b_out
    sgemm_out<<<dim3((N_CLASS + 63)/64, 1), 256>>>(h1f, W_out, out,
                                                   N_CLASS, HID, b_out);
}

// round 4
// speedup vs baseline: 3.6209x; 2.1574x over previous
#include <cuda_runtime.h>
#include <cuda_bf16.h>
#include <cstdint>
#include <math.h>

// ---------------------------------------------------------------------------
// Problem constants
// ---------------------------------------------------------------------------
#define N_CLASS 10000
#define EMB     512
#define HID     1024
#define BATCH   64
#define SEQ     128
#define G4      (4*HID)          // 4096 gate columns (interleaved J = 4u+g)
#define ROWS    (SEQ*BATCH)      // 8192

// ---------------------------------------------------------------------------
// mma.sync / ldmatrix / cp.async helpers (arch-portable sm_80+ path)
// ---------------------------------------------------------------------------
__device__ __forceinline__ uint32_t smem_u32(const void* p) {
    uint32_t a;
    asm("{ .reg .u64 t; cvta.to.shared.u64 t, %1; cvt.u32.u64 %0, t; }"
        : "=r"(a) : "l"(p));
    return a;
}

__device__ __forceinline__ void ldmatrix_x4(uint32_t* r, uint32_t addr) {
    asm volatile("ldmatrix.sync.aligned.m8n8.x4.shared.b16 {%0,%1,%2,%3}, [%4];"
                 : "=r"(r[0]), "=r"(r[1]), "=r"(r[2]), "=r"(r[3]) : "r"(addr));
}

__device__ __forceinline__ void mma16816(float* d, const uint32_t* a,
                                         const uint32_t* b) {
    asm volatile(
        "mma.sync.aligned.m16n8k16.row.col.f32.bf16.bf16.f32 "
        "{%0,%1,%2,%3}, {%4,%5,%6,%7}, {%8,%9}, {%0,%1,%2,%3};"
        : "+f"(d[0]), "+f"(d[1]), "+f"(d[2]), "+f"(d[3])
        : "r"(a[0]), "r"(a[1]), "r"(a[2]), "r"(a[3]),
          "r"(b[0]), "r"(b[1]));
}

__device__ __forceinline__ void cpa16(uint32_t s, const void* g) {
    asm volatile("cp.async.cg.shared.global [%0], [%1], 16;" :: "r"(s), "l"(g));
}
__device__ __forceinline__ void cpa_commit() {
    asm volatile("cp.async.commit_group;");
}
template<int N> __device__ __forceinline__ void cpa_wait() {
    asm volatile("cp.async.wait_group %0;" :: "n"(N));
}

__device__ __forceinline__ float sigf(float x) { return 1.f / (1.f + expf(-x)); }

// ---------------------------------------------------------------------------
// Device scratch (static; no cudaMalloc allowed)
// ---------------------------------------------------------------------------
__device__ __nv_bfloat16 g_Ehi [ROWS*EMB];
__device__ __nv_bfloat16 g_Elo [ROWS*EMB];
__device__ __nv_bfloat16 g_Hhi [ROWS*HID];     // layer0 h: [t][m][u]
__device__ __nv_bfloat16 g_Hlo [ROWS*HID];
__device__ __nv_bfloat16 g_B0hi[G4*EMB];       // input weights L0 [J=4u+g][k]
__device__ __nv_bfloat16 g_B0lo[G4*EMB];
__device__ __nv_bfloat16 g_B1hi[G4*HID];
__device__ __nv_bfloat16 g_B1lo[G4*HID];
__device__ __nv_bfloat16 g_R0hi[G4*HID];       // recurrent weights [J][k]
__device__ __nv_bfloat16 g_R0lo[G4*HID];
__device__ __nv_bfloat16 g_R1hi[G4*HID];
__device__ __nv_bfloat16 g_R1lo[G4*HID];
__device__ float g_XG0[ROWS*G4];
__device__ float g_XG1[ROWS*G4];
__device__ float g_b0 [G4];
__device__ float g_b1 [G4];
__device__ __nv_bfloat16 g_h1ah[BATCH*HID];    // layer1 h ping-pong
__device__ __nv_bfloat16 g_h1al[BATCH*HID];
__device__ __nv_bfloat16 g_h1bh[BATCH*HID];
__device__ __nv_bfloat16 g_h1bl[BATCH*HID];
__device__ __nv_bfloat16 g_hzh [BATCH*HID];    // zero h
__device__ __nv_bfloat16 g_hzl [BATCH*HID];
__device__ float g_h1f [BATCH*HID];            // layer1 final h fp32
__device__ unsigned g_cnt[2];                  // grid-barrier counters

// ---------------------------------------------------------------------------
// Prep kernels
// ---------------------------------------------------------------------------
__global__ void wcvt(const float* __restrict__ W, __nv_bfloat16* __restrict__ Bh,
                     __nv_bfloat16* __restrict__ Bl, int K, int g)
{
    __shared__ float s[32][33];
    int k0 = blockIdx.x * 32, u0 = blockIdx.y * 32;
    int tx = threadIdx.x, ty = threadIdx.y;          // (32, 8)
#pragma unroll
    for (int j = 0; j < 4; j++)
        s[ty + j*8][tx] = W[(size_t)(k0 + ty + j*8) * HID + u0 + tx];
    __syncthreads();
#pragma unroll
    for (int j = 0; j < 4; j++) {
        int uu = ty + j*8;
        float v = s[tx][uu];
        __nv_bfloat16 hi = __float2bfloat16(v);
        size_t o = (size_t)(4*(u0 + uu) + g) * K + k0 + tx;
        Bh[o] = hi;
        Bl[o] = __float2bfloat16(v - __bfloat162float(hi));
    }
}

__global__ void pack_b4(const float* __restrict__ a, const float* __restrict__ b,
                        const float* __restrict__ c, const float* __restrict__ d,
                        float4* __restrict__ dst)
{
    int u = blockIdx.x * blockDim.x + threadIdx.x;
    if (u < HID) dst[u] = make_float4(a[u], b[u], c[u], d[u]);
}

__global__ void zero_init(__nv_bfloat16* __restrict__ hzh,
                          __nv_bfloat16* __restrict__ hzl,
                          unsigned* __restrict__ cnt)
{
    int idx = blockIdx.x * blockDim.x + threadIdx.x;
    if (idx < BATCH * HID) {
        hzh[idx] = __float2bfloat16(0.f);
        hzl[idx] = __float2bfloat16(0.f);
    }
    if (idx < 2) cnt[idx] = 0;
}

__global__ void embed_bf16(const int* __restrict__ X, const float* __restrict__ C,
                           __nv_bfloat16* __restrict__ Eh, __nv_bfloat16* __restrict__ El)
{
    int idx = blockIdx.x * blockDim.x + threadIdx.x;
    if (idx < ROWS * EMB) {
        int row = idx >> 9, e = idx & 511;
        int t = row >> 6, b = row & 63;
        int tok = X[b * SEQ + t];
        float v = C[(size_t)tok * EMB + e];
        __nv_bfloat16 hi = __float2bfloat16(v);
        Eh[idx] = hi;
        El[idx] = __float2bfloat16(v - __bfloat162float(hi));
    }
}

// ---------------------------------------------------------------------------
// HMMA split-bf16 GEMM (unchanged from round 3, known-good):
// C[M][4096] = A[M][K] @ B[4096][K]^T, 128x64 tile, 256 thr.
// ---------------------------------------------------------------------------
__global__ __launch_bounds__(256)
void mm_mma(const __nv_bfloat16* __restrict__ Ah, const __nv_bfloat16* __restrict__ Al,
            const __nv_bfloat16* __restrict__ Bh, const __nv_bfloat16* __restrict__ Bl,
            float* __restrict__ Cm, int K)
{
    __shared__ __align__(16) char sA[2][128*80];
    __shared__ __align__(16) char sB[2][64*80];

    const int tid = threadIdx.x, lane = tid & 31, w = tid >> 5;
    const int m0 = blockIdx.y * 128, n0 = blockIdx.x * 64;
    const int wm = (w & 3) * 32, wn = (w >> 2) * 32;
    const int g = lane >> 2, tig = lane & 3;
    const int sub = lane >> 3, lr = lane & 7;

    float acc[2][4][4];
#pragma unroll
    for (int ti = 0; ti < 2; ti++)
#pragma unroll
        for (int j = 0; j < 4; j++)
#pragma unroll
            for (int q = 0; q < 4; q++) acc[ti][j][q] = 0.f;

    uint32_t aBase[2][2];
#pragma unroll
    for (int hl = 0; hl < 2; hl++)
#pragma unroll
        for (int ti = 0; ti < 2; ti++)
            aBase[hl][ti] = smem_u32(sA) + hl*(128*80)
                          + (wm + ti*16 + (sub & 1)*8 + lr)*80 + (sub >> 1)*16;

    const int nchunk = K >> 5;
    for (int c = 0; c < nchunk; c++) {
        __syncthreads();
        const int kb = c * 32;
#pragma unroll
        for (int i = 0; i < 2; i++) {
            int lin = tid + i * 256;
            int r = lin >> 2, s = lin & 3;
            size_t go = (size_t)(m0 + r) * K + kb + s * 8;
            *(uint4*)(sA[0] + r*80 + s*16) = *(const uint4*)(Ah + go);
            *(uint4*)(sA[1] + r*80 + s*16) = *(const uint4*)(Al + go);
        }
        {
            int r = tid >> 2, s = tid & 3;
            size_t go = (size_t)(n0 + r) * K + kb + s * 8;
            *(uint4*)(sB[0] + r*80 + s*16) = *(const uint4*)(Bh + go);
            *(uint4*)(sB[1] + r*80 + s*16) = *(const uint4*)(Bl + go);
        }
        __syncthreads();

#pragma unroll
        for (int ks = 0; ks < 2; ks++) {
            uint32_t a[2][2][4];
#pragma unroll
            for (int hl = 0; hl < 2; hl++)
#pragma unroll
                for (int ti = 0; ti < 2; ti++)
                    ldmatrix_x4(a[hl][ti], aBase[hl][ti] + ks*32);
            uint32_t bh[4][2], bl[4][2];
#pragma unroll
            for (int j = 0; j < 4; j++) {
                int off = (wn + 8*j + g)*80 + ks*32 + tig*4;
                bh[j][0] = *(const uint32_t*)(sB[0] + off);
                bh[j][1] = *(const uint32_t*)(sB[0] + off + 16);
                bl[j][0] = *(const uint32_t*)(sB[1] + off);
                bl[j][1] = *(const uint32_t*)(sB[1] + off + 16);
            }
#pragma unroll
            for (int ti = 0; ti < 2; ti++)
#pragma unroll
                for (int j = 0; j < 4; j++) {
                    mma16816(acc[ti][j], a[0][ti], bh[j]);
                    mma16816(acc[ti][j], a[0][ti], bl[j]);
                    mma16816(acc[ti][j], a[1][ti], bh[j]);
                }
        }
    }

#pragma unroll
    for (int ti = 0; ti < 2; ti++) {
        int row = m0 + wm + ti*16 + g;
#pragma unroll
        for (int j = 0; j < 4; j++) {
            int col = n0 + wn + 8*j + tig*2;
            *(float2*)&Cm[(size_t)row * G4 + col] =
                make_float2(acc[ti][j][0], acc[ti][j][1]);
            *(float2*)&Cm[(size_t)(row + 8) * G4 + col] =
                make_float2(acc[ti][j][2], acc[ti][j][3]);
        }
    }
}

// ---------------------------------------------------------------------------
// Persistent LSTM recurrence kernel.
// 128 blocks (1/SM, co-resident) x 256 thr (8 warps). Block owns 32 gate
// columns; its weight slice (32x1024, hi+lo) lives in SMEM for all 128 steps.
// Cell state lives in registers. h handoff via global + spin grid barrier.
// A (h_prev) streamed with 3-stage cp.async pipeline (L2 path = coherent).
// ---------------------------------------------------------------------------
#define PW 2064                       // weight smem row pitch (2048 + 16 pad)
#define PA 144                        // A-chunk smem row pitch (128 + 16 pad)
#define W_BYTES (32*PW)               // 66048 per matrix
#define A_STAGE (2*64*PA)             // 18432 (hi+lo per stage)
#define A_OFF   (2*W_BYTES)           // 132096
#define SM_PERSIST (A_OFF + 3*A_STAGE)  // 187392

__global__ __launch_bounds__(256, 1)
void lstm_persist(const __nv_bfloat16* __restrict__ Wh, const __nv_bfloat16* __restrict__ Wl,
                  const float* __restrict__ XG, const float* __restrict__ bias,
                  const __nv_bfloat16* __restrict__ hzh, const __nv_bfloat16* __restrict__ hzl,
                  __nv_bfloat16* __restrict__ HAh, __nv_bfloat16* __restrict__ HAl,
                  __nv_bfloat16* __restrict__ HBh, __nv_bfloat16* __restrict__ HBl,
                  float* __restrict__ hf, unsigned* __restrict__ cnt, int mode)
{
    extern __shared__ __align__(16) char sm[];
    char* sWh = sm;
    char* sWl = sm + W_BYTES;
    const uint32_t aAbs = smem_u32(sm) + A_OFF;

    const int tid = threadIdx.x, lane = tid & 31, w = tid >> 5;
    const int wr = w & 3, wc = w >> 2;
    const int g = lane >> 2, tig = lane & 3;
    const int sub = lane >> 3, lr = lane & 7;
    const int n0 = blockIdx.x * 32;

    // ---- load this block's weight slice into smem (once) ----
    for (int idx = tid; idx < 4096; idx += 256) {
        int r = idx >> 7, s = idx & 127;
        size_t go = ((size_t)(n0 + r) << 10) + s * 8;
        *(uint4*)(sWh + r*PW + s*16) = *(const uint4*)(Wh + go);
        *(uint4*)(sWl + r*PW + s*16) = *(const uint4*)(Wl + go);
    }
    __syncthreads();

    const uint32_t rowoff = (16*wr + (sub & 1)*8 + lr)*PA + (sub >> 1)*16;
    const int brow0 = (wc*16 + g)*PW;
    const int brow1 = (wc*16 + 8 + g)*PW;
    const int m1 = 16*wr + g, m2 = m1 + 8;
    const int Jc0 = n0 + wc*16 + tig*2;
    const int Jc1 = Jc0 + 8;
    const float2 bb0 = *(const float2*)&bias[Jc0];
    const float2 bb1 = *(const float2*)&bias[Jc1];
    const bool co = (tig & 1);
    const int u0 = Jc0 >> 2, u1 = Jc1 >> 2;

    float cc00 = 0.f, cc01 = 0.f, cc10 = 0.f, cc11 = 0.f;  // c state [j][row]
    unsigned tgt = 0;

    for (int t = 0; t < SEQ; t++) {
        const __nv_bfloat16 *ph, *pl;
        __nv_bfloat16 *dh, *dl;
        if (mode == 0) {
            dh = HAh + (size_t)t * BATCH * HID;
            dl = HAl + (size_t)t * BATCH * HID;
            ph = t ? dh - BATCH*HID : hzh;
            pl = t ? dl - BATCH*HID : hzl;
        } else {
            if (t & 1) { dh = HBh; dl = HBl; ph = HAh; pl = HAl; }
            else       { dh = HAh; dl = HAl;
                         ph = t ? HBh : hzh; pl = t ? HBl : hzl; }
        }

        // issue chunk c of h_prev into stage c%3
        auto issue = [&](int c) {
            uint32_t dst = aAbs + (c % 3) * A_STAGE;
#pragma unroll
            for (int i = 0; i < 2; i++) {
                int lin = tid + i * 256;
                int r = lin >> 3, s = lin & 7;
                size_t go = ((size_t)r << 10) + c*64 + s*8;
                cpa16(dst + r*PA + s*16,        ph + go);
                cpa16(dst + 9216 + r*PA + s*16, pl + go);
            }
        };

        issue(0); cpa_commit();
        issue(1); cpa_commit();

        float acc0[4] = {0.f, 0.f, 0.f, 0.f};
        float acc1[4] = {0.f, 0.f, 0.f, 0.f};

        for (int c = 0; c < 16; c++) {
            if (c < 15) cpa_wait<1>(); else cpa_wait<0>();
            __syncthreads();
            if (c + 2 < 16) { issue(c + 2); cpa_commit(); }

            uint32_t ah = aAbs + (c % 3) * A_STAGE + rowoff;
#pragma unroll
            for (int ks = 0; ks < 4; ks++) {
                uint32_t a0[4], a1[4];
                ldmatrix_x4(a0, ah + ks*32);
                ldmatrix_x4(a1, ah + 9216 + ks*32);
                const int ko = c*128 + ks*32 + tig*4;
                uint32_t b0[2], b0l[2], b1[2], b1l[2];
                b0[0]  = *(const uint32_t*)(sWh + brow0 + ko);
                b0[1]  = *(const uint32_t*)(sWh + brow0 + ko + 16);
                b0l[0] = *(const uint32_t*)(sWl + brow0 + ko);
                b0l[1] = *(const uint32_t*)(sWl + brow0 + ko + 16);
                b1[0]  = *(const uint32_t*)(sWh + brow1 + ko);
                b1[1]  = *(const uint32_t*)(sWh + brow1 + ko + 16);
                b1l[0] = *(const uint32_t*)(sWl + brow1 + ko);
                b1l[1] = *(const uint32_t*)(sWl + brow1 + ko + 16);
                mma16816(acc0, a0, b0);
                mma16816(acc0, a0, b0l);
                mma16816(acc0, a1, b0);
                mma16816(acc1, a0, b1);
                mma16816(acc1, a0, b1l);
                mma16816(acc1, a1, b1);
            }
        }

        // ---- pointwise epilogue ----
        {
            const float* xr1 = XG + (((size_t)(t*64 + m1)) << 12) + Jc0;
            const float* xr2 = XG + (((size_t)(t*64 + m2)) << 12) + Jc0;
            float2 x1 = *(const float2*)xr1;
            float2 x2 = *(const float2*)xr2;
            float p0 = acc0[0] + x1.x + bb0.x;
            float p1 = acc0[1] + x1.y + bb0.y;
            float p2 = acc0[2] + x2.x + bb0.x;
            float p3 = acc0[3] + x2.y + bb0.y;
            float a0v = co ? tanhf(p0) : sigf(p0);
            float a1v = sigf(p1);
            float a2v = co ? tanhf(p2) : sigf(p2);
            float a3v = sigf(p3);
            float C1 = __shfl_xor_sync(0xFFFFFFFFu, a0v, 1);
            float O1 = __shfl_xor_sync(0xFFFFFFFFu, a1v, 1);
            float C2 = __shfl_xor_sync(0xFFFFFFFFu, a2v, 1);
            float O2 = __shfl_xor_sync(0xFFFFFFFFu, a3v, 1);
            if (!co) {
                cc00 = a0v * cc00 + a1v * C1;
                float hv = O1 * tanhf(cc00);
                __nv_bfloat16 hh = __float2bfloat16(hv);
                dh[m1*HID + u0] = hh;
                dl[m1*HID + u0] = __float2bfloat16(hv - __bfloat162float(hh));
                if (hf && t == SEQ-1) hf[m1*HID + u0] = hv;
                cc01 = a2v * cc01 + a3v * C2;
                hv = O2 * tanhf(cc01);
                hh = __float2bfloat16(hv);
                dh[m2*HID + u0] = hh;
                dl[m2*HID + u0] = __float2bfloat16(hv - __bfloat162float(hh));
                if (hf && t == SEQ-1) hf[m2*HID + u0] = hv;
            }
        }
        {
            const float* xr1 = XG + (((size_t)(t*64 + m1)) << 12) + Jc1;
            const float* xr2 = XG + (((size_t)(t*64 + m2)) << 12) + Jc1;
            float2 x1 = *(const float2*)xr1;
            float2 x2 = *(const float2*)xr2;
            float p0 = acc1[0] + x1.x + bb1.x;
            float p1 = acc1[1] + x1.y + bb1.y;
            float p2 = acc1[2] + x2.x + bb1.x;
            float p3 = acc1[3] + x2.y + bb1.y;
            float a0v = co ? tanhf(p0) : sigf(p0);
            float a1v = sigf(p1);
            float a2v = co ? tanhf(p2) : sigf(p2);
            float a3v = sigf(p3);
            float C1 = __shfl_xor_sync(0xFFFFFFFFu, a0v, 1);
            float O1 = __shfl_xor_sync(0xFFFFFFFFu, a1v, 1);
            float C2 = __shfl_xor_sync(0xFFFFFFFFu, a2v, 1);
            float O2 = __shfl_xor_sync(0xFFFFFFFFu, a3v, 1);
            if (!co) {
                cc10 = a0v * cc10 + a1v * C1;
                float hv = O1 * tanhf(cc10);
                __nv_bfloat16 hh = __float2bfloat16(hv);
                dh[m1*HID + u1] = hh;
                dl[m1*HID + u1] = __float2bfloat16(hv - __bfloat162float(hh));
                if (hf && t == SEQ-1) hf[m1*HID + u1] = hv;
                cc11 = a2v * cc11 + a3v * C2;
                hv = O2 * tanhf(cc11);
                hh = __float2bfloat16(hv);
                dh[m2*HID + u1] = hh;
                dl[m2*HID + u1] = __float2bfloat16(hv - __bfloat162float(hh));
                if (hf && t == SEQ-1) hf[m2*HID + u1] = hv;
            }
        }

        // ---- grid barrier (skip after last step) ----
        if (t != SEQ-1) {
            tgt += gridDim.x;
            __syncthreads();
            if (tid == 0) {
                __threadfence();
                atomicAdd(cnt, 1u);
                unsigned v;
                do {
                    asm volatile("ld.acquire.gpu.u32 %0, [%1];"
                                 : "=r"(v) : "l"(cnt) : "memory");
                } while (v < tgt);
            }
            __syncthreads();
        }
    }
}

// ---------------------------------------------------------------------------
// Output projection: out[64][N] = A[64][K] @ B[K][N] + bias (fp32)
// ---------------------------------------------------------------------------
__global__ __launch_bounds__(256)
void sgemm_out(const float* __restrict__ A, const float* __restrict__ B,
               float* __restrict__ Cmat, int N, int K, const float* __restrict__ bias)
{
    __shared__ __align__(16) float As[16][68];
    __shared__ __align__(16) float Bs[16][68];

    const int tid = threadIdx.x;
    const int tx = tid & 15, ty = tid >> 4;
    const int n0 = blockIdx.x * 64;

    float acc[4][4];
#pragma unroll
    for (int r = 0; r < 4; r++)
#pragma unroll
        for (int c = 0; c < 4; c++) acc[r][c] = 0.f;

    const int am = tid >> 2;
    const int akg = tid & 3;
    const int bk = tid >> 4;
    const int bn4 = tid & 15;

    for (int k0 = 0; k0 < K; k0 += 16) {
        float4 av = *(const float4*)&A[(size_t)am * K + k0 + akg * 4];
        float4 bv;
        if (n0 + bn4 * 4 < N)
            bv = *(const float4*)&B[(size_t)(k0 + bk) * N + n0 + bn4 * 4];
        else
            bv = make_float4(0.f, 0.f, 0.f, 0.f);
        As[akg*4 + 0][am] = av.x;
        As[akg*4 + 1][am] = av.y;
        As[akg*4 + 2][am] = av.z;
        As[akg*4 + 3][am] = av.w;
        *(float4*)&Bs[bk][bn4 * 4] = bv;
        __syncthreads();
#pragma unroll
        for (int kk = 0; kk < 16; kk++) {
            float4 a4 = *(const float4*)&As[kk][ty * 4];
            float4 b4 = *(const float4*)&Bs[kk][tx * 4];
            acc[0][0] = fmaf(a4.x, b4.x, acc[0][0]);
            acc[0][1] = fmaf(a4.x, b4.y, acc[0][1]);
            acc[0][2] = fmaf(a4.x, b4.z, acc[0][2]);
            acc[0][3] = fmaf(a4.x, b4.w, acc[0][3]);
            acc[1][0] = fmaf(a4.y, b4.x, acc[1][0]);
            acc[1][1] = fmaf(a4.y, b4.y, acc[1][1]);
            acc[1][2] = fmaf(a4.y, b4.z, acc[1][2]);
            acc[1][3] = fmaf(a4.y, b4.w, acc[1][3]);
            acc[2][0] = fmaf(a4.z, b4.x, acc[2][0]);
            acc[2][1] = fmaf(a4.z, b4.y, acc[2][1]);
            acc[2][2] = fmaf(a4.z, b4.z, acc[2][2]);
            acc[2][3] = fmaf(a4.z, b4.w, acc[2][3]);
            acc[3][0] = fmaf(a4.w, b4.x, acc[3][0]);
            acc[3][1] = fmaf(a4.w, b4.y, acc[3][1]);
            acc[3][2] = fmaf(a4.w, b4.z, acc[3][2]);
            acc[3][3] = fmaf(a4.w, b4.w, acc[3][3]);
        }
        __syncthreads();
    }

#pragma unroll
    for (int r = 0; r < 4; r++) {
        int m = ty * 4 + r;
#pragma unroll
        for (int c = 0; c < 4; c++) {
            int n = n0 + tx * 4 + c;
            if (n < N) Cmat[(size_t)m * N + n] = acc[r][c] + bias[n];
        }
    }
}

// ---------------------------------------------------------------------------
// Host launcher (graph-capturable: kernel launches only)
// ---------------------------------------------------------------------------
extern "C" void kernel_launch(void* const* d_in, const int* in_sizes, int n_in,
                              void* d_out, int out_size)
{
    const int*   X     = (const int*)  d_in[0];
    const float* Cemb  = (const float*)d_in[1];
    const float* W_fx  = (const float*)d_in[2];
    const float* W_fh  = (const float*)d_in[3];
    const float* W_ix  = (const float*)d_in[4];
    const float* W_ih  = (const float*)d_in[5];
    const float* W_Cx  = (const float*)d_in[6];
    const float* W_Ch  = (const float*)d_in[7];
    const float* W_ox  = (const float*)d_in[8];
    const float* W_oh  = (const float*)d_in[9];
    const float* W_fx1 = (const float*)d_in[10];
    const float* W_fh1 = (const float*)d_in[11];
    const float* W_ix1 = (const float*)d_in[12];
    const float* W_ih1 = (const float*)d_in[13];   // unused (reference bug kept)
    const float* W_Cx1 = (const float*)d_in[14];
    const float* W_Ch1 = (const float*)d_in[15];
    const float* W_ox1 = (const float*)d_in[16];
    const float* W_oh1 = (const float*)d_in[17];
    const float* W_out = (const float*)d_in[18];
    const float* b_f   = (const float*)d_in[19];
    const float* b_i   = (const float*)d_in[20];
    const float* b_C   = (const float*)d_in[21];
    const float* b_o   = (const float*)d_in[22];
    const float* b_f1  = (const float*)d_in[23];
    const float* b_i1  = (const float*)d_in[24];
    const float* b_C1  = (const float*)d_in[25];
    const float* b_o1  = (const float*)d_in[26];
    const float* b_out = (const float*)d_in[27];
    float* out = (float*)d_out;
    (void)W_ih1; (void)n_in; (void)in_sizes; (void)out_size;

    __nv_bfloat16 *Ehi, *Elo, *Hhi, *Hlo, *B0h, *B0l, *B1h, *B1l;
    __nv_bfloat16 *R0h, *R0l, *R1h, *R1l;
    __nv_bfloat16 *h1ah, *h1al, *h1bh, *h1bl, *hzh, *hzl;
    float *XG0, *XG1, *b0, *b1, *h1f;
    unsigned* cnt;
    cudaGetSymbolAddress((void**)&Ehi, g_Ehi);   cudaGetSymbolAddress((void**)&Elo, g_Elo);
    cudaGetSymbolAddress((void**)&Hhi, g_Hhi);   cudaGetSymbolAddress((void**)&Hlo, g_Hlo);
    cudaGetSymbolAddress((void**)&B0h, g_B0hi);  cudaGetSymbolAddress((void**)&B0l, g_B0lo);
    cudaGetSymbolAddress((void**)&B1h, g_B1hi);  cudaGetSymbolAddress((void**)&B1l, g_B1lo);
    cudaGetSymbolAddress((void**)&R0h, g_R0hi);  cudaGetSymbolAddress((void**)&R0l, g_R0lo);
    cudaGetSymbolAddress((void**)&R1h, g_R1hi);  cudaGetSymbolAddress((void**)&R1l, g_R1lo);
    cudaGetSymbolAddress((void**)&XG0, g_XG0);   cudaGetSymbolAddress((void**)&XG1, g_XG1);
    cudaGetSymbolAddress((void**)&b0, g_b0);     cudaGetSymbolAddress((void**)&b1, g_b1);
    cudaGetSymbolAddress((void**)&h1ah, g_h1ah); cudaGetSymbolAddress((void**)&h1al, g_h1al);
    cudaGetSymbolAddress((void**)&h1bh, g_h1bh); cudaGetSymbolAddress((void**)&h1bl, g_h1bl);
    cudaGetSymbolAddress((void**)&hzh, g_hzh);   cudaGetSymbolAddress((void**)&hzl, g_hzl);
    cudaGetSymbolAddress((void**)&h1f, g_h1f);
    cudaGetSymbolAddress((void**)&cnt, g_cnt);

    cudaFuncSetAttribute(lstm_persist,
                         cudaFuncAttributeMaxDynamicSharedMemorySize, SM_PERSIST);

    dim3 tb(32, 8);
    // Input-side weights: B[J=4u+g][k]
    wcvt<<<dim3(EMB/32, HID/32), tb>>>(W_fx,  B0h, B0l, EMB, 0);
    wcvt<<<dim3(EMB/32, HID/32), tb>>>(W_ix,  B0h, B0l, EMB, 1);
    wcvt<<<dim3(EMB/32, HID/32), tb>>>(W_Cx,  B0h, B0l, EMB, 2);
    wcvt<<<dim3(EMB/32, HID/32), tb>>>(W_ox,  B0h, B0l, EMB, 3);
    wcvt<<<dim3(HID/32, HID/32), tb>>>(W_fx1, B1h, B1l, HID, 0);
    wcvt<<<dim3(HID/32, HID/32), tb>>>(W_ix1, B1h, B1l, HID, 1);
    wcvt<<<dim3(HID/32, HID/32), tb>>>(W_Cx1, B1h, B1l, HID, 2);
    wcvt<<<dim3(HID/32, HID/32), tb>>>(W_ox1, B1h, B1l, HID, 3);
    // Recurrent weights (layer1 i-gate reuses layer0 W_ih — reference bug kept)
    wcvt<<<dim3(HID/32, HID/32), tb>>>(W_fh,  R0h, R0l, HID, 0);
    wcvt<<<dim3(HID/32, HID/32), tb>>>(W_ih,  R0h, R0l, HID, 1);
    wcvt<<<dim3(HID/32, HID/32), tb>>>(W_Ch,  R0h, R0l, HID, 2);
    wcvt<<<dim3(HID/32, HID/32), tb>>>(W_oh,  R0h, R0l, HID, 3);
    wcvt<<<dim3(HID/32, HID/32), tb>>>(W_fh1, R1h, R1l, HID, 0);
    wcvt<<<dim3(HID/32, HID/32), tb>>>(W_ih,  R1h, R1l, HID, 1);
    wcvt<<<dim3(HID/32, HID/32), tb>>>(W_Ch1, R1h, R1l, HID, 2);
    wcvt<<<dim3(HID/32, HID/32), tb>>>(W_oh1, R1h, R1l, HID, 3);
    pack_b4<<<(HID + 255)/256, 256>>>(b_f,  b_i,  b_C,  b_o,  (float4*)b0);
    pack_b4<<<(HID + 255)/256, 256>>>(b_f1, b_i1, b_C1, b_o1, (float4*)b1);

    zero_init<<<(BATCH*HID + 255)/256, 256>>>(hzh, hzl, cnt);
    embed_bf16<<<(ROWS*EMB + 255)/256, 256>>>(X, Cemb, Ehi, Elo);

    // XG0 = E @ Wx0 (HMMA)
    mm_mma<<<dim3(G4/64, ROWS/128), 256>>>(Ehi, Elo, B0h, B0l, XG0, EMB);

    // Layer 0 recurrence: ONE persistent kernel, 128 grid-synced steps
    lstm_persist<<<128, 256, SM_PERSIST>>>(R0h, R0l, XG0, b0, hzh, hzl,
                                           Hhi, Hlo, nullptr, nullptr,
                                           nullptr, cnt + 0, 0);

    // XG1 = H @ Wx1 (HMMA)
    mm_mma<<<dim3(G4/64, ROWS/128), 256>>>(Hhi, Hlo, B1h, B1l, XG1, HID);

    // Layer 1 recurrence: persistent, ping-pong h buffers
    lstm_persist<<<128, 256, SM_PERSIST>>>(R1h, R1l, XG1, b1, hzh, hzl,
                                           h1ah, h1al, h1bh, h1bl,
                                           h1f, cnt + 1, 1);

    // out = h1 @ W_out + b_out
    sgemm_out<<<dim3((N_CLASS + 63)/64, 1), 256>>>(h1f, W_out, out,
                                                   N_CLASS, HID, b_out);
}

// round 5
// speedup vs baseline: 3.7693x; 1.0410x over previous
#include <cuda_runtime.h>
#include <cuda_bf16.h>
#include <cstdint>
#include <math.h>

// ---------------------------------------------------------------------------
// Problem constants
// ---------------------------------------------------------------------------
#define N_CLASS 10000
#define EMB     512
#define HID     1024
#define BATCH   64
#define SEQ     128
#define G4      (4*HID)          // 4096 gate columns (interleaved J = 4u+g)
#define ROWS    (SEQ*BATCH)      // 8192

// ---------------------------------------------------------------------------
// mma.sync / ldmatrix / cp.async helpers (arch-portable sm_80+ path)
// ---------------------------------------------------------------------------
__device__ __forceinline__ uint32_t smem_u32(const void* p) {
    uint32_t a;
    asm("{ .reg .u64 t; cvta.to.shared.u64 t, %1; cvt.u32.u64 %0, t; }"
        : "=r"(a) : "l"(p));
    return a;
}

__device__ __forceinline__ void ldmatrix_x4(uint32_t* r, uint32_t addr) {
    asm volatile("ldmatrix.sync.aligned.m8n8.x4.shared.b16 {%0,%1,%2,%3}, [%4];"
                 : "=r"(r[0]), "=r"(r[1]), "=r"(r[2]), "=r"(r[3]) : "r"(addr));
}

__device__ __forceinline__ void mma16816(float* d, const uint32_t* a,
                                         const uint32_t* b) {
    asm volatile(
        "mma.sync.aligned.m16n8k16.row.col.f32.bf16.bf16.f32 "
        "{%0,%1,%2,%3}, {%4,%5,%6,%7}, {%8,%9}, {%0,%1,%2,%3};"
        : "+f"(d[0]), "+f"(d[1]), "+f"(d[2]), "+f"(d[3])
        : "r"(a[0]), "r"(a[1]), "r"(a[2]), "r"(a[3]),
          "r"(b[0]), "r"(b[1]));
}

__device__ __forceinline__ void cpa16(uint32_t s, const void* g) {
    asm volatile("cp.async.cg.shared.global [%0], [%1], 16;" :: "r"(s), "l"(g));
}
__device__ __forceinline__ void cpa_commit() {
    asm volatile("cp.async.commit_group;");
}
template<int N> __device__ __forceinline__ void cpa_wait() {
    asm volatile("cp.async.wait_group %0;" :: "n"(N));
}

__device__ __forceinline__ void st_release(unsigned* p, unsigned v) {
    asm volatile("st.release.gpu.u32 [%0], %1;" :: "l"(p), "r"(v) : "memory");
}
__device__ __forceinline__ unsigned ld_acquire(const unsigned* p) {
    unsigned v;
    asm volatile("ld.acquire.gpu.u32 %0, [%1];" : "=r"(v) : "l"(p) : "memory");
    return v;
}

__device__ __forceinline__ float sigf(float x) { return 1.f / (1.f + expf(-x)); }

// ---------------------------------------------------------------------------
// Device scratch (static; no cudaMalloc allowed)
// ---------------------------------------------------------------------------
__device__ __nv_bfloat16 g_Ehi [ROWS*EMB];
__device__ __nv_bfloat16 g_Elo [ROWS*EMB];
__device__ __nv_bfloat16 g_Hhi [ROWS*HID];     // layer0 h: [t][m][u]
__device__ __nv_bfloat16 g_Hlo [ROWS*HID];
__device__ __nv_bfloat16 g_B0hi[G4*EMB];       // input weights L0 [J=4u+g][k]
__device__ __nv_bfloat16 g_B0lo[G4*EMB];
__device__ __nv_bfloat16 g_B1hi[G4*HID];
__device__ __nv_bfloat16 g_B1lo[G4*HID];
__device__ __nv_bfloat16 g_R0hi[G4*HID];       // recurrent weights [J][k]
__device__ __nv_bfloat16 g_R0lo[G4*HID];
__device__ __nv_bfloat16 g_R1hi[G4*HID];
__device__ __nv_bfloat16 g_R1lo[G4*HID];
__device__ float g_XG0[ROWS*G4];
__device__ float g_XG1[ROWS*G4];
__device__ float g_b0 [G4];
__device__ float g_b1 [G4];
__device__ __nv_bfloat16 g_h1ah[BATCH*HID];    // layer1 h ping-pong
__device__ __nv_bfloat16 g_h1al[BATCH*HID];
__device__ __nv_bfloat16 g_h1bh[BATCH*HID];
__device__ __nv_bfloat16 g_h1bl[BATCH*HID];
__device__ __nv_bfloat16 g_hzh [BATCH*HID];    // zero h
__device__ __nv_bfloat16 g_hzl [BATCH*HID];
__device__ float g_h1f [BATCH*HID];            // layer1 final h fp32
__device__ unsigned g_flags[2*128*8];          // tree-barrier arrival flags
__device__ unsigned g_go[2*8];                 // tree-barrier go words

// ---------------------------------------------------------------------------
// Prep kernels
// ---------------------------------------------------------------------------
struct WcvtArgs {
    const float* src[16];
    __nv_bfloat16* dh[16];
    __nv_bfloat16* dl[16];
    int K[16];
    int g[16];
};

// W[K][1024](fp32, col u) -> dst[4u+g][K] split bf16; one launch for all 16.
__global__ void wcvt_all(WcvtArgs a)
{
    __shared__ float s[32][33];
    const int z = blockIdx.z;
    const int K = a.K[z];
    const int k0 = blockIdx.x * 32;
    if (k0 >= K) return;
    const float* W = a.src[z];
    __nv_bfloat16* Bh = a.dh[z];
    __nv_bfloat16* Bl = a.dl[z];
    const int g = a.g[z];
    const int u0 = blockIdx.y * 32;
    const int tx = threadIdx.x, ty = threadIdx.y;        // (32, 8)
#pragma unroll
    for (int j = 0; j < 4; j++)
        s[ty + j*8][tx] = W[(size_t)(k0 + ty + j*8) * HID + u0 + tx];
    __syncthreads();
#pragma unroll
    for (int j = 0; j < 4; j++) {
        int uu = ty + j*8;
        float v = s[tx][uu];
        __nv_bfloat16 hi = __float2bfloat16(v);
        size_t o = (size_t)(4*(u0 + uu) + g) * K + k0 + tx;
        Bh[o] = hi;
        Bl[o] = __float2bfloat16(v - __bfloat162float(hi));
    }
}

__global__ void pack_b4(const float* __restrict__ a, const float* __restrict__ b,
                        const float* __restrict__ c, const float* __restrict__ d,
                        float4* __restrict__ dst)
{
    int u = blockIdx.x * blockDim.x + threadIdx.x;
    if (u < HID) dst[u] = make_float4(a[u], b[u], c[u], d[u]);
}

__global__ void zero_init(__nv_bfloat16* __restrict__ hzh,
                          __nv_bfloat16* __restrict__ hzl,
                          unsigned* __restrict__ flags,
                          unsigned* __restrict__ go)
{
    int idx = blockIdx.x * blockDim.x + threadIdx.x;
    if (idx < BATCH * HID) {
        hzh[idx] = __float2bfloat16(0.f);
        hzl[idx] = __float2bfloat16(0.f);
    }
    if (idx < 2*128*8) flags[idx] = 0;
    if (idx < 2*8) go[idx] = 0;
}

__global__ void embed_bf16(const int* __restrict__ X, const float* __restrict__ C,
                           __nv_bfloat16* __restrict__ Eh, __nv_bfloat16* __restrict__ El)
{
    int idx = blockIdx.x * blockDim.x + threadIdx.x;
    if (idx < ROWS * EMB) {
        int row = idx >> 9, e = idx & 511;
        int t = row >> 6, b = row & 63;
        int tok = X[b * SEQ + t];
        float v = C[(size_t)tok * EMB + e];
        __nv_bfloat16 hi = __float2bfloat16(v);
        Eh[idx] = hi;
        El[idx] = __float2bfloat16(v - __bfloat162float(hi));
    }
}

// ---------------------------------------------------------------------------
// HMMA split-bf16 GEMM with 2-stage cp.async pipeline:
// C[M][4096] = A[M][K] @ B[4096][K]^T, 128x64 tile, 256 thr.
// Stage layout: [0,10240) A-hi, [10240,20480) A-lo, [20480,25600) B-hi,
// [25600,30720) B-lo. 2 stages = 61440 B dynamic smem (2 blocks/SM).
// ---------------------------------------------------------------------------
#define MM_STAGE 30720
#define MM_SMEM  (2*MM_STAGE)
__global__ __launch_bounds__(256)
void mm_mma(const __nv_bfloat16* __restrict__ Ah, const __nv_bfloat16* __restrict__ Al,
            const __nv_bfloat16* __restrict__ Bh, const __nv_bfloat16* __restrict__ Bl,
            float* __restrict__ Cm, int K)
{
    extern __shared__ __align__(16) char smc[];
    const int tid = threadIdx.x, lane = tid & 31, w = tid >> 5;
    const int m0 = blockIdx.y * 128, n0 = blockIdx.x * 64;
    const int wm = (w & 3) * 32, wn = (w >> 2) * 32;
    const int g = lane >> 2, tig = lane & 3;
    const int sub = lane >> 3, lr = lane & 7;
    const uint32_t sbase = smem_u32(smc);

    float acc[2][4][4];
#pragma unroll
    for (int ti = 0; ti < 2; ti++)
#pragma unroll
        for (int j = 0; j < 4; j++)
#pragma unroll
            for (int q = 0; q < 4; q++) acc[ti][j][q] = 0.f;

    uint32_t aOff[2][2];   // [hi/lo][mtile], relative to stage base
#pragma unroll
    for (int hl = 0; hl < 2; hl++)
#pragma unroll
        for (int ti = 0; ti < 2; ti++)
            aOff[hl][ti] = hl*10240
                         + (wm + ti*16 + (sub & 1)*8 + lr)*80 + (sub >> 1)*16;

    const int ar = tid >> 2, as4 = tid & 3;

    auto issue = [&](int c) {
        uint32_t base = sbase + (c & 1) * MM_STAGE;
        size_t kb = (size_t)c * 32;
#pragma unroll
        for (int i = 0; i < 2; i++) {
            int r = ar + i * 64;
            size_t go = (size_t)(m0 + r) * K + kb + as4 * 8;
            cpa16(base + r*80 + as4*16,         Ah + go);
            cpa16(base + 10240 + r*80 + as4*16, Al + go);
        }
        {
            size_t go = (size_t)(n0 + ar) * K + kb + as4 * 8;
            cpa16(base + 20480 + ar*80 + as4*16, Bh + go);
            cpa16(base + 25600 + ar*80 + as4*16, Bl + go);
        }
        cpa_commit();
    };

    issue(0);
    const int nchunk = K >> 5;
    for (int c = 0; c < nchunk; c++) {
        __syncthreads();                 // stage (c+1)&1 free for refill
        if (c + 1 < nchunk) { issue(c + 1); cpa_wait<1>(); }
        else                { cpa_wait<0>(); }
        __syncthreads();                 // cp.async data visible to all

        const uint32_t st = sbase + (c & 1) * MM_STAGE;
#pragma unroll
        for (int ks = 0; ks < 2; ks++) {
            uint32_t a[2][2][4];
#pragma unroll
            for (int hl = 0; hl < 2; hl++)
#pragma unroll
                for (int ti = 0; ti < 2; ti++)
                    ldmatrix_x4(a[hl][ti], st + aOff[hl][ti] + ks*32);
            uint32_t bh[4][2], bl[4][2];
#pragma unroll
            for (int j = 0; j < 4; j++) {
                uint32_t off = st + 20480 + (wn + 8*j + g)*80 + ks*32 + tig*4;
                bh[j][0] = *(const uint32_t*)(smc + (off - sbase));
                bh[j][1] = *(const uint32_t*)(smc + (off - sbase) + 16);
                bl[j][0] = *(const uint32_t*)(smc + (off - sbase) + 5120);
                bl[j][1] = *(const uint32_t*)(smc + (off - sbase) + 5120 + 16);
            }
#pragma unroll
            for (int ti = 0; ti < 2; ti++)
#pragma unroll
                for (int j = 0; j < 4; j++) {
                    mma16816(acc[ti][j], a[0][ti], bh[j]);
                    mma16816(acc[ti][j], a[0][ti], bl[j]);
                    mma16816(acc[ti][j], a[1][ti], bh[j]);
                }
        }
    }

#pragma unroll
    for (int ti = 0; ti < 2; ti++) {
        int row = m0 + wm + ti*16 + g;
#pragma unroll
        for (int j = 0; j < 4; j++) {
            int col = n0 + wn + 8*j + tig*2;
            *(float2*)&Cm[(size_t)row * G4 + col] =
                make_float2(acc[ti][j][0], acc[ti][j][1]);
            *(float2*)&Cm[(size_t)(row + 8) * G4 + col] =
                make_float2(acc[ti][j][2], acc[ti][j][3]);
        }
    }
}

// ---------------------------------------------------------------------------
// Persistent LSTM recurrence kernel (as round 4) with:
//  - two-level tree grid barrier (parallel flags + go word)
//  - xg prefetched at step top (independent of the MMA chain)
// ---------------------------------------------------------------------------
#define PW 2064                       // weight smem row pitch (2048 + 16 pad)
#define PA 144                        // A-chunk smem row pitch (128 + 16 pad)
#define W_BYTES (32*PW)               // 66048 per matrix
#define A_STAGE (2*64*PA)             // 18432 (hi+lo per stage)
#define A_OFF   (2*W_BYTES)           // 132096
#define SM_PERSIST (A_OFF + 3*A_STAGE)  // 187392

__global__ __launch_bounds__(256, 1)
void lstm_persist(const __nv_bfloat16* __restrict__ Wh, const __nv_bfloat16* __restrict__ Wl,
                  const float* __restrict__ XG, const float* __restrict__ bias,
                  const __nv_bfloat16* __restrict__ hzh, const __nv_bfloat16* __restrict__ hzl,
                  __nv_bfloat16* __restrict__ HAh, __nv_bfloat16* __restrict__ HAl,
                  __nv_bfloat16* __restrict__ HBh, __nv_bfloat16* __restrict__ HBl,
                  float* __restrict__ hf,
                  unsigned* __restrict__ flags, unsigned* __restrict__ go, int mode)
{
    extern __shared__ __align__(16) char sm[];
    char* sWh = sm;
    char* sWl = sm + W_BYTES;
    const uint32_t aAbs = smem_u32(sm) + A_OFF;

    const int tid = threadIdx.x, lane = tid & 31, w = tid >> 5;
    const int wr = w & 3, wc = w >> 2;
    const int g = lane >> 2, tig = lane & 3;
    const int sub = lane >> 3, lr = lane & 7;
    const int n0 = blockIdx.x * 32;

    // ---- load this block's weight slice into smem (once) ----
    for (int idx = tid; idx < 4096; idx += 256) {
        int r = idx >> 7, s = idx & 127;
        size_t gof = ((size_t)(n0 + r) << 10) + s * 8;
        *(uint4*)(sWh + r*PW + s*16) = *(const uint4*)(Wh + gof);
        *(uint4*)(sWl + r*PW + s*16) = *(const uint4*)(Wl + gof);
    }
    __syncthreads();

    const uint32_t rowoff = (16*wr + (sub & 1)*8 + lr)*PA + (sub >> 1)*16;
    const int brow0 = (wc*16 + g)*PW;
    const int brow1 = (wc*16 + 8 + g)*PW;
    const int m1 = 16*wr + g, m2 = m1 + 8;
    const int Jc0 = n0 + wc*16 + tig*2;
    const int Jc1 = Jc0 + 8;
    const float2 bb0 = *(const float2*)&bias[Jc0];
    const float2 bb1 = *(const float2*)&bias[Jc1];
    const bool co = (tig & 1);
    const int u0 = Jc0 >> 2, u1 = Jc1 >> 2;

    float cc00 = 0.f, cc01 = 0.f, cc10 = 0.f, cc11 = 0.f;

    for (int t = 0; t < SEQ; t++) {
        const __nv_bfloat16 *ph, *pl;
        __nv_bfloat16 *dh, *dl;
        if (mode == 0) {
            dh = HAh + (size_t)t * BATCH * HID;
            dl = HAl + (size_t)t * BATCH * HID;
            ph = t ? dh - BATCH*HID : hzh;
            pl = t ? dl - BATCH*HID : hzl;
        } else {
            if (t & 1) { dh = HBh; dl = HBl; ph = HAh; pl = HAl; }
            else       { dh = HAh; dl = HAl;
                         ph = t ? HBh : hzh; pl = t ? HBl : hzl; }
        }

        // prefetch xg for this step (independent of the recurrence chain)
        const float* xb = XG + (((size_t)(t*64)) << 12);
        const float2 x1_0 = *(const float2*)(xb + (size_t)m1*G4 + Jc0);
        const float2 x2_0 = *(const float2*)(xb + (size_t)m2*G4 + Jc0);
        const float2 x1_1 = *(const float2*)(xb + (size_t)m1*G4 + Jc1);
        const float2 x2_1 = *(const float2*)(xb + (size_t)m2*G4 + Jc1);

        auto issue = [&](int c) {
            uint32_t dst = aAbs + (c % 3) * A_STAGE;
#pragma unroll
            for (int i = 0; i < 2; i++) {
                int lin = tid + i * 256;
                int r = lin >> 3, s = lin & 7;
                size_t gof = ((size_t)r << 10) + c*64 + s*8;
                cpa16(dst + r*PA + s*16,        ph + gof);
                cpa16(dst + 9216 + r*PA + s*16, pl + gof);
            }
        };

        issue(0); cpa_commit();
        issue(1); cpa_commit();

        float acc0[4] = {0.f, 0.f, 0.f, 0.f};
        float acc1[4] = {0.f, 0.f, 0.f, 0.f};

        for (int c = 0; c < 16; c++) {
            if (c < 15) cpa_wait<1>(); else cpa_wait<0>();
            __syncthreads();
            if (c + 2 < 16) { issue(c + 2); cpa_commit(); }

            uint32_t ah = aAbs + (c % 3) * A_STAGE + rowoff;
#pragma unroll
            for (int ks = 0; ks < 4; ks++) {
                uint32_t a0[4], a1[4];
                ldmatrix_x4(a0, ah + ks*32);
                ldmatrix_x4(a1, ah + 9216 + ks*32);
                const int ko = c*128 + ks*32 + tig*4;
                uint32_t b0[2], b0l[2], b1[2], b1l[2];
                b0[0]  = *(const uint32_t*)(sWh + brow0 + ko);
                b0[1]  = *(const uint32_t*)(sWh + brow0 + ko + 16);
                b0l[0] = *(const uint32_t*)(sWl + brow0 + ko);
                b0l[1] = *(const uint32_t*)(sWl + brow0 + ko + 16);
                b1[0]  = *(const uint32_t*)(sWh + brow1 + ko);
                b1[1]  = *(const uint32_t*)(sWh + brow1 + ko + 16);
                b1l[0] = *(const uint32_t*)(sWl + brow1 + ko);
                b1l[1] = *(const uint32_t*)(sWl + brow1 + ko + 16);
                mma16816(acc0, a0, b0);
                mma16816(acc0, a0, b0l);
                mma16816(acc0, a1, b0);
                mma16816(acc1, a0, b1);
                mma16816(acc1, a0, b1l);
                mma16816(acc1, a1, b1);
            }
        }

        // ---- pointwise epilogue ----
        {
            float p0 = acc0[0] + x1_0.x + bb0.x;
            float p1 = acc0[1] + x1_0.y + bb0.y;
            float p2 = acc0[2] + x2_0.x + bb0.x;
            float p3 = acc0[3] + x2_0.y + bb0.y;
            float a0v = co ? tanhf(p0) : sigf(p0);
            float a1v = sigf(p1);
            float a2v = co ? tanhf(p2) : sigf(p2);
            float a3v = sigf(p3);
            float C1 = __shfl_xor_sync(0xFFFFFFFFu, a0v, 1);
            float O1 = __shfl_xor_sync(0xFFFFFFFFu, a1v, 1);
            float C2 = __shfl_xor_sync(0xFFFFFFFFu, a2v, 1);
            float O2 = __shfl_xor_sync(0xFFFFFFFFu, a3v, 1);
            if (!co) {
                cc00 = a0v * cc00 + a1v * C1;
                float hv = O1 * tanhf(cc00);
                __nv_bfloat16 hh = __float2bfloat16(hv);
                dh[m1*HID + u0] = hh;
                dl[m1*HID + u0] = __float2bfloat16(hv - __bfloat162float(hh));
                if (hf && t == SEQ-1) hf[m1*HID + u0] = hv;
                cc01 = a2v * cc01 + a3v * C2;
                hv = O2 * tanhf(cc01);
                hh = __float2bfloat16(hv);
                dh[m2*HID + u0] = hh;
                dl[m2*HID + u0] = __float2bfloat16(hv - __bfloat162float(hh));
                if (hf && t == SEQ-1) hf[m2*HID + u0] = hv;
            }
        }
        {
            float p0 = acc1[0] + x1_1.x + bb1.x;
            float p1 = acc1[1] + x1_1.y + bb1.y;
            float p2 = acc1[2] + x2_1.x + bb1.x;
            float p3 = acc1[3] + x2_1.y + bb1.y;
            float a0v = co ? tanhf(p0) : sigf(p0);
            float a1v = sigf(p1);
            float a2v = co ? tanhf(p2) : sigf(p2);
            float a3v = sigf(p3);
            float C1 = __shfl_xor_sync(0xFFFFFFFFu, a0v, 1);
            float O1 = __shfl_xor_sync(0xFFFFFFFFu, a1v, 1);
            float C2 = __shfl_xor_sync(0xFFFFFFFFu, a2v, 1);
            float O2 = __shfl_xor_sync(0xFFFFFFFFu, a3v, 1);
            if (!co) {
                cc10 = a0v * cc10 + a1v * C1;
                float hv = O1 * tanhf(cc10);
                __nv_bfloat16 hh = __float2bfloat16(hv);
                dh[m1*HID + u1] = hh;
                dl[m1*HID + u1] = __float2bfloat16(hv - __bfloat162float(hh));
                if (hf && t == SEQ-1) hf[m1*HID + u1] = hv;
                cc11 = a2v * cc11 + a3v * C2;
                hv = O2 * tanhf(cc11);
                hh = __float2bfloat16(hv);
                dh[m2*HID + u1] = hh;
                dl[m2*HID + u1] = __float2bfloat16(hv - __bfloat162float(hh));
                if (hf && t == SEQ-1) hf[m2*HID + u1] = hv;
            }
        }

        // ---- two-level tree grid barrier (skip after last step) ----
        if (t != SEQ-1) {
            const unsigned sense = (unsigned)(t + 1);
            __syncthreads();                      // all h stores done, block-wide
            if (blockIdx.x == 0) {
                if (tid >= 1 && tid < 128) {
                    const unsigned* f = flags + tid*8;
                    while (ld_acquire(f) < sense) {}
                }
                __syncthreads();
                if (tid == 0) st_release(go, sense);
            } else {
                if (tid == 0) {
                    st_release(flags + blockIdx.x*8, sense);
                    while (ld_acquire(go) < sense) {}
                }
                __syncthreads();
            }
        }
    }
}

// ---------------------------------------------------------------------------
// Output projection: out[64][N] = A[64][K] @ B[K][N] + bias (fp32)
// ---------------------------------------------------------------------------
__global__ __launch_bounds__(256)
void sgemm_out(const float* __restrict__ A, const float* __restrict__ B,
               float* __restrict__ Cmat, int N, int K, const float* __restrict__ bias)
{
    __shared__ __align__(16) float As[16][68];
    __shared__ __align__(16) float Bs[16][68];

    const int tid = threadIdx.x;
    const int tx = tid & 15, ty = tid >> 4;
    const int n0 = blockIdx.x * 64;

    float acc[4][4];
#pragma unroll
    for (int r = 0; r < 4; r++)
#pragma unroll
        for (int c = 0; c < 4; c++) acc[r][c] = 0.f;

    const int am = tid >> 2;
    const int akg = tid & 3;
    const int bk = tid >> 4;
    const int bn4 = tid & 15;

    for (int k0 = 0; k0 < K; k0 += 16) {
        float4 av = *(const float4*)&A[(size_t)am * K + k0 + akg * 4];
        float4 bv;
        if (n0 + bn4 * 4 < N)
            bv = *(const float4*)&B[(size_t)(k0 + bk) * N + n0 + bn4 * 4];
        else
            bv = make_float4(0.f, 0.f, 0.f, 0.f);
        As[akg*4 + 0][am] = av.x;
        As[akg*4 + 1][am] = av.y;
        As[akg*4 + 2][am] = av.z;
        As[akg*4 + 3][am] = av.w;
        *(float4*)&Bs[bk][bn4 * 4] = bv;
        __syncthreads();
#pragma unroll
        for (int kk = 0; kk < 16; kk++) {
            float4 a4 = *(const float4*)&As[kk][ty * 4];
            float4 b4 = *(const float4*)&Bs[kk][tx * 4];
            acc[0][0] = fmaf(a4.x, b4.x, acc[0][0]);
            acc[0][1] = fmaf(a4.x, b4.y, acc[0][1]);
            acc[0][2] = fmaf(a4.x, b4.z, acc[0][2]);
            acc[0][3] = fmaf(a4.x, b4.w, acc[0][3]);
            acc[1][0] = fmaf(a4.y, b4.x, acc[1][0]);
            acc[1][1] = fmaf(a4.y, b4.y, acc[1][1]);
            acc[1][2] = fmaf(a4.y, b4.z, acc[1][2]);
            acc[1][3] = fmaf(a4.y, b4.w, acc[1][3]);
            acc[2][0] = fmaf(a4.z, b4.x, acc[2][0]);
            acc[2][1] = fmaf(a4.z, b4.y, acc[2][1]);
            acc[2][2] = fmaf(a4.z, b4.z, acc[2][2]);
            acc[2][3] = fmaf(a4.z, b4.w, acc[2][3]);
            acc[3][0] = fmaf(a4.w, b4.x, acc[3][0]);
            acc[3][1] = fmaf(a4.w, b4.y, acc[3][1]);
            acc[3][2] = fmaf(a4.w, b4.z, acc[3][2]);
            acc[3][3] = fmaf(a4.w, b4.w, acc[3][3]);
        }
        __syncthreads();
    }

#pragma unroll
    for (int r = 0; r < 4; r++) {
        int m = ty * 4 + r;
#pragma unroll
        for (int c = 0; c < 4; c++) {
            int n = n0 + tx * 4 + c;
            if (n < N) Cmat[(size_t)m * N + n] = acc[r][c] + bias[n];
        }
    }
}

// ---------------------------------------------------------------------------
// Host launcher (graph-capturable: kernel launches only)
// ---------------------------------------------------------------------------
extern "C" void kernel_launch(void* const* d_in, const int* in_sizes, int n_in,
                              void* d_out, int out_size)
{
    const int*   X     = (const int*)  d_in[0];
    const float* Cemb  = (const float*)d_in[1];
    const float* W_fx  = (const float*)d_in[2];
    const float* W_fh  = (const float*)d_in[3];
    const float* W_ix  = (const float*)d_in[4];
    const float* W_ih  = (const float*)d_in[5];
    const float* W_Cx  = (const float*)d_in[6];
    const float* W_Ch  = (const float*)d_in[7];
    const float* W_ox  = (const float*)d_in[8];
    const float* W_oh  = (const float*)d_in[9];
    const float* W_fx1 = (const float*)d_in[10];
    const float* W_fh1 = (const float*)d_in[11];
    const float* W_ix1 = (const float*)d_in[12];
    const float* W_ih1 = (const float*)d_in[13];   // unused (reference bug kept)
    const float* W_Cx1 = (const float*)d_in[14];
    const float* W_Ch1 = (const float*)d_in[15];
    const float* W_ox1 = (const float*)d_in[16];
    const float* W_oh1 = (const float*)d_in[17];
    const float* W_out = (const float*)d_in[18];
    const float* b_f   = (const float*)d_in[19];
    const float* b_i   = (const float*)d_in[20];
    const float* b_C   = (const float*)d_in[21];
    const float* b_o   = (const float*)d_in[22];
    const float* b_f1  = (const float*)d_in[23];
    const float* b_i1  = (const float*)d_in[24];
    const float* b_C1  = (const float*)d_in[25];
    const float* b_o1  = (const float*)d_in[26];
    const float* b_out = (const float*)d_in[27];
    float* out = (float*)d_out;
    (void)W_ih1; (void)n_in; (void)in_sizes; (void)out_size;

    __nv_bfloat16 *Ehi, *Elo, *Hhi, *Hlo, *B0h, *B0l, *B1h, *B1l;
    __nv_bfloat16 *R0h, *R0l, *R1h, *R1l;
    __nv_bfloat16 *h1ah, *h1al, *h1bh, *h1bl, *hzh, *hzl;
    float *XG0, *XG1, *b0, *b1, *h1f;
    unsigned *flags, *go;
    cudaGetSymbolAddress((void**)&Ehi, g_Ehi);   cudaGetSymbolAddress((void**)&Elo, g_Elo);
    cudaGetSymbolAddress((void**)&Hhi, g_Hhi);   cudaGetSymbolAddress((void**)&Hlo, g_Hlo);
    cudaGetSymbolAddress((void**)&B0h, g_B0hi);  cudaGetSymbolAddress((void**)&B0l, g_B0lo);
    cudaGetSymbolAddress((void**)&B1h, g_B1hi);  cudaGetSymbolAddress((void**)&B1l, g_B1lo);
    cudaGetSymbolAddress((void**)&R0h, g_R0hi);  cudaGetSymbolAddress((void**)&R0l, g_R0lo);
    cudaGetSymbolAddress((void**)&R1h, g_R1hi);  cudaGetSymbolAddress((void**)&R1l, g_R1lo);
    cudaGetSymbolAddress((void**)&XG0, g_XG0);   cudaGetSymbolAddress((void**)&XG1, g_XG1);
    cudaGetSymbolAddress((void**)&b0, g_b0);     cudaGetSymbolAddress((void**)&b1, g_b1);
    cudaGetSymbolAddress((void**)&h1ah, g_h1ah); cudaGetSymbolAddress((void**)&h1al, g_h1al);
    cudaGetSymbolAddress((void**)&h1bh, g_h1bh); cudaGetSymbolAddress((void**)&h1bl, g_h1bl);
    cudaGetSymbolAddress((void**)&hzh, g_hzh);   cudaGetSymbolAddress((void**)&hzl, g_hzl);
    cudaGetSymbolAddress((void**)&h1f, g_h1f);
    cudaGetSymbolAddress((void**)&flags, g_flags);
    cudaGetSymbolAddress((void**)&go,   g_go);

    cudaFuncSetAttribute(lstm_persist,
                         cudaFuncAttributeMaxDynamicSharedMemorySize, SM_PERSIST);
    cudaFuncSetAttribute(mm_mma,
                         cudaFuncAttributeMaxDynamicSharedMemorySize, MM_SMEM);

    // All 16 weight conversions in one launch
    WcvtArgs wa;
    const float* srcs[16] = {W_fx, W_ix, W_Cx, W_ox,
                             W_fx1, W_ix1, W_Cx1, W_ox1,
                             W_fh,  W_ih,  W_Ch,  W_oh,
                             W_fh1, W_ih,  W_Ch1, W_oh1};  // layer1 i-gate = W_ih (ref bug)
    for (int z = 0; z < 16; z++) {
        wa.src[z] = srcs[z];
        wa.g[z] = z & 3;
        if (z < 4)       { wa.dh[z] = B0h; wa.dl[z] = B0l; wa.K[z] = EMB; }
        else if (z < 8)  { wa.dh[z] = B1h; wa.dl[z] = B1l; wa.K[z] = HID; }
        else if (z < 12) { wa.dh[z] = R0h; wa.dl[z] = R0l; wa.K[z] = HID; }
        else             { wa.dh[z] = R1h; wa.dl[z] = R1l; wa.K[z] = HID; }
    }
    wcvt_all<<<dim3(32, 32, 16), dim3(32, 8)>>>(wa);

    pack_b4<<<(HID + 255)/256, 256>>>(b_f,  b_i,  b_C,  b_o,  (float4*)b0);
    pack_b4<<<(HID + 255)/256, 256>>>(b_f1, b_i1, b_C1, b_o1, (float4*)b1);

    zero_init<<<(BATCH*HID + 255)/256, 256>>>(hzh, hzl, flags, go);
    embed_bf16<<<(ROWS*EMB + 255)/256, 256>>>(X, Cemb, Ehi, Elo);

    // XG0 = E @ Wx0 (HMMA, pipelined)
    mm_mma<<<dim3(G4/64, ROWS/128), 256, MM_SMEM>>>(Ehi, Elo, B0h, B0l, XG0, EMB);

    // Layer 0 recurrence: persistent, 128 grid-synced steps
    lstm_persist<<<128, 256, SM_PERSIST>>>(R0h, R0l, XG0, b0, hzh, hzl,
                                           Hhi, Hlo, nullptr, nullptr,
                                           nullptr, flags, go, 0);

    // XG1 = H @ Wx1 (HMMA, pipelined)
    mm_mma<<<dim3(G4/64, ROWS/128), 256, MM_SMEM>>>(Hhi, Hlo, B1h, B1l, XG1, HID);

    // Layer 1 recurrence: persistent, ping-pong h buffers
    lstm_persist<<<128, 256, SM_PERSIST>>>(R1h, R1l, XG1, b1, hzh, hzl,
                                           h1ah, h1al, h1bh, h1bl,
                                           h1f, flags + 128*8, go + 8, 1);

    // out = h1 @ W_out + b_out
    sgemm_out<<<dim3((N_CLASS + 63)/64, 1), 256>>>(h1f, W_out, out,
                                                   N_CLASS, HID, b_out);
}

// round 6
// speedup vs baseline: 5.5667x; 1.4769x over previous
#include <cuda_runtime.h>
#include <cuda_fp16.h>
#include <cstdint>
#include <math.h>

// ---------------------------------------------------------------------------
// Problem constants
// ---------------------------------------------------------------------------
#define N_CLASS 10000
#define EMB     512
#define HID     1024
#define BATCH   64
#define SEQ     128
#define G4      (4*HID)          // 4096 gate columns (interleaved J = 4u+g)
#define ROWS    (SEQ*BATCH)      // 8192

// ---------------------------------------------------------------------------
// mma.sync / ldmatrix / cp.async helpers (arch-portable sm_80+ path)
// ---------------------------------------------------------------------------
__device__ __forceinline__ uint32_t smem_u32(const void* p) {
    uint32_t a;
    asm("{ .reg .u64 t; cvta.to.shared.u64 t, %1; cvt.u32.u64 %0, t; }"
        : "=r"(a) : "l"(p));
    return a;
}

__device__ __forceinline__ void ldmatrix_x4(uint32_t* r, uint32_t addr) {
    asm volatile("ldmatrix.sync.aligned.m8n8.x4.shared.b16 {%0,%1,%2,%3}, [%4];"
                 : "=r"(r[0]), "=r"(r[1]), "=r"(r[2]), "=r"(r[3]) : "r"(addr));
}

// D(f32) += A(f16) * B(f16), m16n8k16, A row-major, B col-major
__device__ __forceinline__ void mma16816(float* d, const uint32_t* a,
                                         const uint32_t* b) {
    asm volatile(
        "mma.sync.aligned.m16n8k16.row.col.f32.f16.f16.f32 "
        "{%0,%1,%2,%3}, {%4,%5,%6,%7}, {%8,%9}, {%0,%1,%2,%3};"
        : "+f"(d[0]), "+f"(d[1]), "+f"(d[2]), "+f"(d[3])
        : "r"(a[0]), "r"(a[1]), "r"(a[2]), "r"(a[3]),
          "r"(b[0]), "r"(b[1]));
}

__device__ __forceinline__ void cpa16(uint32_t s, const void* g) {
    asm volatile("cp.async.cg.shared.global [%0], [%1], 16;" :: "r"(s), "l"(g));
}
__device__ __forceinline__ void cpa_commit() {
    asm volatile("cp.async.commit_group;");
}
template<int N> __device__ __forceinline__ void cpa_wait() {
    asm volatile("cp.async.wait_group %0;" :: "n"(N));
}

__device__ __forceinline__ void st_release(unsigned* p, unsigned v) {
    asm volatile("st.release.gpu.u32 [%0], %1;" :: "l"(p), "r"(v) : "memory");
}
__device__ __forceinline__ unsigned ld_acquire(const unsigned* p) {
    unsigned v;
    asm volatile("ld.acquire.gpu.u32 %0, [%1];" : "=r"(v) : "l"(p) : "memory");
    return v;
}

__device__ __forceinline__ float sigf(float x) { return 1.f / (1.f + expf(-x)); }

// ---------------------------------------------------------------------------
// Device scratch (static; no cudaMalloc allowed)
// ---------------------------------------------------------------------------
__device__ __half g_E  [ROWS*EMB];      // embeddings fp16, row = t*64+b
__device__ __half g_H  [ROWS*HID];      // layer0 h: [t][m][u] fp16
__device__ __half g_B0 [G4*EMB];        // input weights L0 [J=4u+g][k]
__device__ __half g_B1 [G4*HID];        // input weights L1
__device__ __half g_R0 [G4*HID];        // recurrent weights L0 [J][k]
__device__ __half g_R1 [G4*HID];        // recurrent weights L1
__device__ float g_XG0[ROWS*G4];
__device__ float g_XG1[ROWS*G4];
__device__ float g_b0 [G4];
__device__ float g_b1 [G4];
__device__ __half g_h1a[BATCH*HID];     // layer1 h ping-pong
__device__ __half g_h1b[BATCH*HID];
__device__ __half g_hz [BATCH*HID];     // zero h
__device__ float g_h1f [BATCH*HID];     // layer1 final h fp32
__device__ unsigned g_flags[2*128*8];   // tree-barrier arrival flags
__device__ unsigned g_go[2*8];          // tree-barrier go words

// ---------------------------------------------------------------------------
// Prep kernels
// ---------------------------------------------------------------------------
struct WcvtArgs {
    const float* src[16];
    __half* dst[16];
    int K[16];
    int g[16];
};

// W[K][1024](fp32, col u) -> dst[4u+g][K] fp16; one launch for all 16 mats.
__global__ void wcvt_all(WcvtArgs a)
{
    __shared__ float s[32][33];
    const int z = blockIdx.z;
    const int K = a.K[z];
    const int k0 = blockIdx.x * 32;
    if (k0 >= K) return;
    const float* W = a.src[z];
    __half* B = a.dst[z];
    const int g = a.g[z];
    const int u0 = blockIdx.y * 32;
    const int tx = threadIdx.x, ty = threadIdx.y;        // (32, 8)
#pragma unroll
    for (int j = 0; j < 4; j++)
        s[ty + j*8][tx] = W[(size_t)(k0 + ty + j*8) * HID + u0 + tx];
    __syncthreads();
#pragma unroll
    for (int j = 0; j < 4; j++) {
        int uu = ty + j*8;
        B[(size_t)(4*(u0 + uu) + g) * K + k0 + tx] = __float2half(s[tx][uu]);
    }
}

__global__ void pack_b4(const float* __restrict__ a, const float* __restrict__ b,
                        const float* __restrict__ c, const float* __restrict__ d,
                        float4* __restrict__ dst)
{
    int u = blockIdx.x * blockDim.x + threadIdx.x;
    if (u < HID) dst[u] = make_float4(a[u], b[u], c[u], d[u]);
}

__global__ void zero_init(__half* __restrict__ hz,
                          unsigned* __restrict__ flags,
                          unsigned* __restrict__ go)
{
    int idx = blockIdx.x * blockDim.x + threadIdx.x;
    if (idx < BATCH * HID) hz[idx] = __float2half(0.f);
    if (idx < 2*128*8) flags[idx] = 0;
    if (idx < 2*8) go[idx] = 0;
}

__global__ void embed_f16(const int* __restrict__ X, const float* __restrict__ C,
                          __half* __restrict__ E)
{
    int idx = blockIdx.x * blockDim.x + threadIdx.x;
    if (idx < ROWS * EMB) {
        int row = idx >> 9, e = idx & 511;
        int t = row >> 6, b = row & 63;
        int tok = X[b * SEQ + t];
        E[idx] = __float2half(C[(size_t)tok * EMB + e]);
    }
}

// ---------------------------------------------------------------------------
// HMMA fp16 GEMM with 2-stage cp.async pipeline:
// C[M][4096] = A[M][K] @ B[4096][K]^T, 128x64 tile, 256 thr.
// Stage: [0,10240) A (128 rows x 80B), [10240,15360) B (64 rows x 80B).
// ---------------------------------------------------------------------------
#define MM_STAGE 15360
#define MM_SMEM  (2*MM_STAGE)
__global__ __launch_bounds__(256)
void mm_mma(const __half* __restrict__ Ag, const __half* __restrict__ Bg,
            float* __restrict__ Cm, int K)
{
    extern __shared__ __align__(16) char smc[];
    const int tid = threadIdx.x, lane = tid & 31, w = tid >> 5;
    const int m0 = blockIdx.y * 128, n0 = blockIdx.x * 64;
    const int wm = (w & 3) * 32, wn = (w >> 2) * 32;
    const int g = lane >> 2, tig = lane & 3;
    const int sub = lane >> 3, lr = lane & 7;
    const uint32_t sbase = smem_u32(smc);

    float acc[2][4][4];
#pragma unroll
    for (int ti = 0; ti < 2; ti++)
#pragma unroll
        for (int j = 0; j < 4; j++)
#pragma unroll
            for (int q = 0; q < 4; q++) acc[ti][j][q] = 0.f;

    uint32_t aOff[2];   // [mtile], relative to stage base
#pragma unroll
    for (int ti = 0; ti < 2; ti++)
        aOff[ti] = (wm + ti*16 + (sub & 1)*8 + lr)*80 + (sub >> 1)*16;

    const int ar = tid >> 2, as4 = tid & 3;

    auto issue = [&](int c) {
        uint32_t base = sbase + (c & 1) * MM_STAGE;
        size_t kb = (size_t)c * 32;
#pragma unroll
        for (int i = 0; i < 2; i++) {
            int r = ar + i * 64;
            cpa16(base + r*80 + as4*16, Ag + (size_t)(m0 + r) * K + kb + as4*8);
        }
        cpa16(base + 10240 + ar*80 + as4*16,
              Bg + (size_t)(n0 + ar) * K + kb + as4*8);
        cpa_commit();
    };

    issue(0);
    const int nchunk = K >> 5;
    for (int c = 0; c < nchunk; c++) {
        __syncthreads();                 // stage (c+1)&1 free for refill
        if (c + 1 < nchunk) { issue(c + 1); cpa_wait<1>(); }
        else                { cpa_wait<0>(); }
        __syncthreads();                 // cp.async data visible to all

        const uint32_t st = sbase + (c & 1) * MM_STAGE;
        const uint32_t stRel = (c & 1) * MM_STAGE;
#pragma unroll
        for (int ks = 0; ks < 2; ks++) {
            uint32_t a[2][4];
#pragma unroll
            for (int ti = 0; ti < 2; ti++)
                ldmatrix_x4(a[ti], st + aOff[ti] + ks*32);
            uint32_t bh[4][2];
#pragma unroll
            for (int j = 0; j < 4; j++) {
                uint32_t off = stRel + 10240 + (wn + 8*j + g)*80 + ks*32 + tig*4;
                bh[j][0] = *(const uint32_t*)(smc + off);
                bh[j][1] = *(const uint32_t*)(smc + off + 16);
            }
#pragma unroll
            for (int ti = 0; ti < 2; ti++)
#pragma unroll
                for (int j = 0; j < 4; j++)
                    mma16816(acc[ti][j], a[ti], bh[j]);
        }
    }

#pragma unroll
    for (int ti = 0; ti < 2; ti++) {
        int row = m0 + wm + ti*16 + g;
#pragma unroll
        for (int j = 0; j < 4; j++) {
            int col = n0 + wn + 8*j + tig*2;
            *(float2*)&Cm[(size_t)row * G4 + col] =
                make_float2(acc[ti][j][0], acc[ti][j][1]);
            *(float2*)&Cm[(size_t)(row + 8) * G4 + col] =
                make_float2(acc[ti][j][2], acc[ti][j][3]);
        }
    }
}

// ---------------------------------------------------------------------------
// Persistent LSTM recurrence kernel (fp16 single-term).
// 128 blocks x 256 thr. Block owns 32 gate columns; weight slice (32x1024
// fp16 = 66KB) in smem for all 128 steps. c in registers. h handoff via
// global + two-level tree barrier. h_prev streamed via 3-stage cp.async.
// ---------------------------------------------------------------------------
#define PW 2064                       // weight smem row pitch (2048 + 16 pad)
#define PA 144                        // A-chunk smem row pitch (128 + 16 pad)
#define W_BYTES (32*PW)               // 66048
#define A_STAGE (64*PA)               // 9216 per stage
#define A_OFF   W_BYTES
#define SM_PERSIST (A_OFF + 3*A_STAGE)  // 93696

__global__ __launch_bounds__(256, 1)
void lstm_persist(const __half* __restrict__ Wg,
                  const float* __restrict__ XG, const float* __restrict__ bias,
                  const __half* __restrict__ hz,
                  __half* __restrict__ HA, __half* __restrict__ HB,
                  float* __restrict__ hf,
                  unsigned* __restrict__ flags, unsigned* __restrict__ go, int mode)
{
    extern __shared__ __align__(16) char sm[];
    char* sW = sm;
    const uint32_t aAbs = smem_u32(sm) + A_OFF;

    const int tid = threadIdx.x, lane = tid & 31, w = tid >> 5;
    const int wr = w & 3, wc = w >> 2;
    const int g = lane >> 2, tig = lane & 3;
    const int sub = lane >> 3, lr = lane & 7;
    const int n0 = blockIdx.x * 32;

    // ---- load this block's weight slice into smem (once) ----
    for (int idx = tid; idx < 4096; idx += 256) {
        int r = idx >> 7, s = idx & 127;
        *(uint4*)(sW + r*PW + s*16) =
            *(const uint4*)(Wg + ((size_t)(n0 + r) << 10) + s*8);
    }
    __syncthreads();

    const uint32_t rowoff = (16*wr + (sub & 1)*8 + lr)*PA + (sub >> 1)*16;
    const int brow0 = (wc*16 + g)*PW;
    const int brow1 = (wc*16 + 8 + g)*PW;
    const int m1 = 16*wr + g, m2 = m1 + 8;
    const int Jc0 = n0 + wc*16 + tig*2;
    const int Jc1 = Jc0 + 8;
    const float2 bb0 = *(const float2*)&bias[Jc0];
    const float2 bb1 = *(const float2*)&bias[Jc1];
    const bool co = (tig & 1);
    const int u0 = Jc0 >> 2, u1 = Jc1 >> 2;

    float cc00 = 0.f, cc01 = 0.f, cc10 = 0.f, cc11 = 0.f;

    for (int t = 0; t < SEQ; t++) {
        const __half* ph;
        __half* dh;
        if (mode == 0) {
            dh = HA + (size_t)t * BATCH * HID;
            ph = t ? dh - BATCH*HID : hz;
        } else {
            if (t & 1) { dh = HB; ph = HA; }
            else       { dh = HA; ph = t ? HB : hz; }
        }

        // prefetch xg for this step (independent of the recurrence chain)
        const float* xb = XG + (((size_t)(t*64)) << 12);
        const float2 x1_0 = *(const float2*)(xb + (size_t)m1*G4 + Jc0);
        const float2 x2_0 = *(const float2*)(xb + (size_t)m2*G4 + Jc0);
        const float2 x1_1 = *(const float2*)(xb + (size_t)m1*G4 + Jc1);
        const float2 x2_1 = *(const float2*)(xb + (size_t)m2*G4 + Jc1);

        auto issue = [&](int c) {
            uint32_t dst = aAbs + (c % 3) * A_STAGE;
#pragma unroll
            for (int i = 0; i < 2; i++) {
                int lin = tid + i * 256;
                int r = lin >> 3, s = lin & 7;
                cpa16(dst + r*PA + s*16, ph + ((size_t)r << 10) + c*64 + s*8);
            }
        };

        issue(0); cpa_commit();
        issue(1); cpa_commit();

        float acc0[4] = {0.f, 0.f, 0.f, 0.f};
        float acc1[4] = {0.f, 0.f, 0.f, 0.f};

        for (int c = 0; c < 16; c++) {
            if (c < 15) cpa_wait<1>(); else cpa_wait<0>();
            __syncthreads();
            if (c + 2 < 16) { issue(c + 2); cpa_commit(); }

            uint32_t ah = aAbs + (c % 3) * A_STAGE + rowoff;
#pragma unroll
            for (int ks = 0; ks < 4; ks++) {
                uint32_t a0[4];
                ldmatrix_x4(a0, ah + ks*32);
                const int ko = c*128 + ks*32 + tig*4;
                uint32_t b0[2], b1[2];
                b0[0] = *(const uint32_t*)(sW + brow0 + ko);
                b0[1] = *(const uint32_t*)(sW + brow0 + ko + 16);
                b1[0] = *(const uint32_t*)(sW + brow1 + ko);
                b1[1] = *(const uint32_t*)(sW + brow1 + ko + 16);
                mma16816(acc0, a0, b0);
                mma16816(acc1, a0, b1);
            }
        }

        // ---- pointwise epilogue ----
        {
            float p0 = acc0[0] + x1_0.x + bb0.x;
            float p1 = acc0[1] + x1_0.y + bb0.y;
            float p2 = acc0[2] + x2_0.x + bb0.x;
            float p3 = acc0[3] + x2_0.y + bb0.y;
            float a0v = co ? tanhf(p0) : sigf(p0);
            float a1v = sigf(p1);
            float a2v = co ? tanhf(p2) : sigf(p2);
            float a3v = sigf(p3);
            float C1 = __shfl_xor_sync(0xFFFFFFFFu, a0v, 1);
            float O1 = __shfl_xor_sync(0xFFFFFFFFu, a1v, 1);
            float C2 = __shfl_xor_sync(0xFFFFFFFFu, a2v, 1);
            float O2 = __shfl_xor_sync(0xFFFFFFFFu, a3v, 1);
            if (!co) {
                cc00 = a0v * cc00 + a1v * C1;
                float hv = O1 * tanhf(cc00);
                dh[m1*HID + u0] = __float2half(hv);
                if (hf && t == SEQ-1) hf[m1*HID + u0] = hv;
                cc01 = a2v * cc01 + a3v * C2;
                hv = O2 * tanhf(cc01);
                dh[m2*HID + u0] = __float2half(hv);
                if (hf && t == SEQ-1) hf[m2*HID + u0] = hv;
            }
        }
        {
            float p0 = acc1[0] + x1_1.x + bb1.x;
            float p1 = acc1[1] + x1_1.y + bb1.y;
            float p2 = acc1[2] + x2_1.x + bb1.x;
            float p3 = acc1[3] + x2_1.y + bb1.y;
            float a0v = co ? tanhf(p0) : sigf(p0);
            float a1v = sigf(p1);
            float a2v = co ? tanhf(p2) : sigf(p2);
            float a3v = sigf(p3);
            float C1 = __shfl_xor_sync(0xFFFFFFFFu, a0v, 1);
            float O1 = __shfl_xor_sync(0xFFFFFFFFu, a1v, 1);
            float C2 = __shfl_xor_sync(0xFFFFFFFFu, a2v, 1);
            float O2 = __shfl_xor_sync(0xFFFFFFFFu, a3v, 1);
            if (!co) {
                cc10 = a0v * cc10 + a1v * C1;
                float hv = O1 * tanhf(cc10);
                dh[m1*HID + u1] = __float2half(hv);
                if (hf && t == SEQ-1) hf[m1*HID + u1] = hv;
                cc11 = a2v * cc11 + a3v * C2;
                hv = O2 * tanhf(cc11);
                dh[m2*HID + u1] = __float2half(hv);
                if (hf && t == SEQ-1) hf[m2*HID + u1] = hv;
            }
        }

        // ---- two-level tree grid barrier (skip after last step) ----
        if (t != SEQ-1) {
            const unsigned sense = (unsigned)(t + 1);
            __syncthreads();                      // all h stores done, block-wide
            if (blockIdx.x == 0) {
                if (tid >= 1 && tid < 128) {
                    const unsigned* f = flags + tid*8;
                    while (ld_acquire(f) < sense) {}
                }
                __syncthreads();
                if (tid == 0) st_release(go, sense);
            } else {
                if (tid == 0) {
                    st_release(flags + blockIdx.x*8, sense);
                    while (ld_acquire(go) < sense) {}
                }
                __syncthreads();
            }
        }
    }
}

// ---------------------------------------------------------------------------
// Output projection: out[64][N] = A[64][K] @ B[K][N] + bias (fp32)
// ---------------------------------------------------------------------------
__global__ __launch_bounds__(256)
void sgemm_out(const float* __restrict__ A, const float* __restrict__ B,
               float* __restrict__ Cmat, int N, int K, const float* __restrict__ bias)
{
    __shared__ __align__(16) float As[16][68];
    __shared__ __align__(16) float Bs[16][68];

    const int tid = threadIdx.x;
    const int tx = tid & 15, ty = tid >> 4;
    const int n0 = blockIdx.x * 64;

    float acc[4][4];
#pragma unroll
    for (int r = 0; r < 4; r++)
#pragma unroll
        for (int c = 0; c < 4; c++) acc[r][c] = 0.f;

    const int am = tid >> 2;
    const int akg = tid & 3;
    const int bk = tid >> 4;
    const int bn4 = tid & 15;

    for (int k0 = 0; k0 < K; k0 += 16) {
        float4 av = *(const float4*)&A[(size_t)am * K + k0 + akg * 4];
        float4 bv;
        if (n0 + bn4 * 4 < N)
            bv = *(const float4*)&B[(size_t)(k0 + bk) * N + n0 + bn4 * 4];
        else
            bv = make_float4(0.f, 0.f, 0.f, 0.f);
        As[akg*4 + 0][am] = av.x;
        As[akg*4 + 1][am] = av.y;
        As[akg*4 + 2][am] = av.z;
        As[akg*4 + 3][am] = av.w;
        *(float4*)&Bs[bk][bn4 * 4] = bv;
        __syncthreads();
#pragma unroll
        for (int kk = 0; kk < 16; kk++) {
            float4 a4 = *(const float4*)&As[kk][ty * 4];
            float4 b4 = *(const float4*)&Bs[kk][tx * 4];
            acc[0][0] = fmaf(a4.x, b4.x, acc[0][0]);
            acc[0][1] = fmaf(a4.x, b4.y, acc[0][1]);
            acc[0][2] = fmaf(a4.x, b4.z, acc[0][2]);
            acc[0][3] = fmaf(a4.x, b4.w, acc[0][3]);
            acc[1][0] = fmaf(a4.y, b4.x, acc[1][0]);
            acc[1][1] = fmaf(a4.y, b4.y, acc[1][1]);
            acc[1][2] = fmaf(a4.y, b4.z, acc[1][2]);
            acc[1][3] = fmaf(a4.y, b4.w, acc[1][3]);
            acc[2][0] = fmaf(a4.z, b4.x, acc[2][0]);
            acc[2][1] = fmaf(a4.z, b4.y, acc[2][1]);
            acc[2][2] = fmaf(a4.z, b4.z, acc[2][2]);
            acc[2][3] = fmaf(a4.z, b4.w, acc[2][3]);
            acc[3][0] = fmaf(a4.w, b4.x, acc[3][0]);
            acc[3][1] = fmaf(a4.w, b4.y, acc[3][1]);
            acc[3][2] = fmaf(a4.w, b4.z, acc[3][2]);
            acc[3][3] = fmaf(a4.w, b4.w, acc[3][3]);
        }
        __syncthreads();
    }

#pragma unroll
    for (int r = 0; r < 4; r++) {
        int m = ty * 4 + r;
#pragma unroll
        for (int c = 0; c < 4; c++) {
            int n = n0 + tx * 4 + c;
            if (n < N) Cmat[(size_t)m * N + n] = acc[r][c] + bias[n];
        }
    }
}

// ---------------------------------------------------------------------------
// Host launcher (graph-capturable: kernel launches only)
// ---------------------------------------------------------------------------
extern "C" void kernel_launch(void* const* d_in, const int* in_sizes, int n_in,
                              void* d_out, int out_size)
{
    const int*   X     = (const int*)  d_in[0];
    const float* Cemb  = (const float*)d_in[1];
    const float* W_fx  = (const float*)d_in[2];
    const float* W_fh  = (const float*)d_in[3];
    const float* W_ix  = (const float*)d_in[4];
    const float* W_ih  = (const float*)d_in[5];
    const float* W_Cx  = (const float*)d_in[6];
    const float* W_Ch  = (const float*)d_in[7];
    const float* W_ox  = (const float*)d_in[8];
    const float* W_oh  = (const float*)d_in[9];
    const float* W_fx1 = (const float*)d_in[10];
    const float* W_fh1 = (const float*)d_in[11];
    const float* W_ix1 = (const float*)d_in[12];
    const float* W_ih1 = (const float*)d_in[13];   // unused (reference bug kept)
    const float* W_Cx1 = (const float*)d_in[14];
    const float* W_Ch1 = (const float*)d_in[15];
    const float* W_ox1 = (const float*)d_in[16];
    const float* W_oh1 = (const float*)d_in[17];
    const float* W_out = (const float*)d_in[18];
    const float* b_f   = (const float*)d_in[19];
    const float* b_i   = (const float*)d_in[20];
    const float* b_C   = (const float*)d_in[21];
    const float* b_o   = (const float*)d_in[22];
    const float* b_f1  = (const float*)d_in[23];
    const float* b_i1  = (const float*)d_in[24];
    const float* b_C1  = (const float*)d_in[25];
    const float* b_o1  = (const float*)d_in[26];
    const float* b_out = (const float*)d_in[27];
    float* out = (float*)d_out;
    (void)W_ih1; (void)n_in; (void)in_sizes; (void)out_size;

    __half *E, *H, *B0, *B1, *R0, *R1, *h1a, *h1b, *hz;
    float *XG0, *XG1, *b0, *b1, *h1f;
    unsigned *flags, *go;
    cudaGetSymbolAddress((void**)&E,  g_E);
    cudaGetSymbolAddress((void**)&H,  g_H);
    cudaGetSymbolAddress((void**)&B0, g_B0);
    cudaGetSymbolAddress((void**)&B1, g_B1);
    cudaGetSymbolAddress((void**)&R0, g_R0);
    cudaGetSymbolAddress((void**)&R1, g_R1);
    cudaGetSymbolAddress((void**)&XG0, g_XG0);
    cudaGetSymbolAddress((void**)&XG1, g_XG1);
    cudaGetSymbolAddress((void**)&b0, g_b0);
    cudaGetSymbolAddress((void**)&b1, g_b1);
    cudaGetSymbolAddress((void**)&h1a, g_h1a);
    cudaGetSymbolAddress((void**)&h1b, g_h1b);
    cudaGetSymbolAddress((void**)&hz,  g_hz);
    cudaGetSymbolAddress((void**)&h1f, g_h1f);
    cudaGetSymbolAddress((void**)&flags, g_flags);
    cudaGetSymbolAddress((void**)&go,   g_go);

    cudaFuncSetAttribute(lstm_persist,
                         cudaFuncAttributeMaxDynamicSharedMemorySize, SM_PERSIST);
    cudaFuncSetAttribute(mm_mma,
                         cudaFuncAttributeMaxDynamicSharedMemorySize, MM_SMEM);

    // All 16 weight conversions in one launch
    WcvtArgs wa;
    const float* srcs[16] = {W_fx, W_ix, W_Cx, W_ox,
                             W_fx1, W_ix1, W_Cx1, W_ox1,
                             W_fh,  W_ih,  W_Ch,  W_oh,
                             W_fh1, W_ih,  W_Ch1, W_oh1};  // layer1 i-gate = W_ih (ref bug)
    for (int z = 0; z < 16; z++) {
        wa.src[z] = srcs[z];
        wa.g[z] = z & 3;
        if (z < 4)       { wa.dst[z] = B0; wa.K[z] = EMB; }
        else if (z < 8)  { wa.dst[z] = B1; wa.K[z] = HID; }
        else if (z < 12) { wa.dst[z] = R0; wa.K[z] = HID; }
        else             { wa.dst[z] = R1; wa.K[z] = HID; }
    }
    wcvt_all<<<dim3(32, 32, 16), dim3(32, 8)>>>(wa);

    pack_b4<<<(HID + 255)/256, 256>>>(b_f,  b_i,  b_C,  b_o,  (float4*)b0);
    pack_b4<<<(HID + 255)/256, 256>>>(b_f1, b_i1, b_C1, b_o1, (float4*)b1);

    zero_init<<<(BATCH*HID + 255)/256, 256>>>(hz, flags, go);
    embed_f16<<<(ROWS*EMB + 255)/256, 256>>>(X, Cemb, E);

    // XG0 = E @ Wx0 (fp16 HMMA, pipelined)
    mm_mma<<<dim3(G4/64, ROWS/128), 256, MM_SMEM>>>(E, B0, XG0, EMB);

    // Layer 0 recurrence: persistent, 128 grid-synced steps
    lstm_persist<<<128, 256, SM_PERSIST>>>(R0, XG0, b0, hz,
                                           H, nullptr, nullptr,
                                           flags, go, 0);

    // XG1 = H @ Wx1 (fp16 HMMA, pipelined)
    mm_mma<<<dim3(G4/64, ROWS/128), 256, MM_SMEM>>>(H, B1, XG1, HID);

    // Layer 1 recurrence: persistent, ping-pong h buffers
    lstm_persist<<<128, 256, SM_PERSIST>>>(R1, XG1, b1, hz,
                                           h1a, h1b, h1f,
                                           flags + 128*8, go + 8, 1);

    // out = h1 @ W_out + b_out
    sgemm_out<<<dim3((N_CLASS + 63)/64, 1), 256>>>(h1f, W_out, out,
                                                   N_CLASS, HID, b_out);
}

// round 7
// speedup vs baseline: 6.2859x; 1.1292x over previous
#include <cuda_runtime.h>
#include <cuda_fp16.h>
#include <cstdint>
#include <math.h>

// ---------------------------------------------------------------------------
// Problem constants
// ---------------------------------------------------------------------------
#define N_CLASS 10000
#define EMB     512
#define HID     1024
#define BATCH   64
#define SEQ     128
#define G4      (4*HID)          // 4096 gate columns (interleaved J = 4u+g)
#define ROWS    (SEQ*BATCH)      // 8192

// ---------------------------------------------------------------------------
// mma.sync / ldmatrix / cp.async helpers (arch-portable sm_80+ path)
// ---------------------------------------------------------------------------
__device__ __forceinline__ uint32_t smem_u32(const void* p) {
    uint32_t a;
    asm("{ .reg .u64 t; cvta.to.shared.u64 t, %1; cvt.u32.u64 %0, t; }"
        : "=r"(a) : "l"(p));
    return a;
}

__device__ __forceinline__ void ldmatrix_x4(uint32_t* r, uint32_t addr) {
    asm volatile("ldmatrix.sync.aligned.m8n8.x4.shared.b16 {%0,%1,%2,%3}, [%4];"
                 : "=r"(r[0]), "=r"(r[1]), "=r"(r[2]), "=r"(r[3]) : "r"(addr));
}

// D(f32) += A(f16) * B(f16), m16n8k16, A row-major, B col-major
__device__ __forceinline__ void mma16816(float* d, const uint32_t* a,
                                         const uint32_t* b) {
    asm volatile(
        "mma.sync.aligned.m16n8k16.row.col.f32.f16.f16.f32 "
        "{%0,%1,%2,%3}, {%4,%5,%6,%7}, {%8,%9}, {%0,%1,%2,%3};"
        : "+f"(d[0]), "+f"(d[1]), "+f"(d[2]), "+f"(d[3])
        : "r"(a[0]), "r"(a[1]), "r"(a[2]), "r"(a[3]),
          "r"(b[0]), "r"(b[1]));
}

__device__ __forceinline__ void cpa16(uint32_t s, const void* g) {
    asm volatile("cp.async.cg.shared.global [%0], [%1], 16;" :: "r"(s), "l"(g));
}
__device__ __forceinline__ void cpa_commit() {
    asm volatile("cp.async.commit_group;");
}
template<int N> __device__ __forceinline__ void cpa_wait() {
    asm volatile("cp.async.wait_group %0;" :: "n"(N));
}

__device__ __forceinline__ void st_release(unsigned* p, unsigned v) {
    asm volatile("st.release.gpu.u32 [%0], %1;" :: "l"(p), "r"(v) : "memory");
}
__device__ __forceinline__ unsigned ld_acquire(const unsigned* p) {
    unsigned v;
    asm volatile("ld.acquire.gpu.u32 %0, [%1];" : "=r"(v) : "l"(p) : "memory");
    return v;
}

__device__ __forceinline__ float sigf(float x) { return 1.f / (1.f + expf(-x)); }

// ---------------------------------------------------------------------------
// Device scratch (static; no cudaMalloc allowed)
// ---------------------------------------------------------------------------
__device__ __half g_E  [ROWS*EMB];      // embeddings fp16, row = t*64+b
__device__ __half g_H  [ROWS*HID];      // layer0 h: [t][m][u] fp16
__device__ __half g_B0 [G4*EMB];        // input weights L0 [J=4u+g][k]
__device__ __half g_B1 [G4*HID];        // input weights L1
__device__ __half g_R0 [G4*HID];        // recurrent weights L0 [J][k]
__device__ __half g_R1 [G4*HID];        // recurrent weights L1
__device__ float g_XG0[ROWS*G4];
__device__ float g_XG1[ROWS*G4];
__device__ float g_b0 [G4];
__device__ float g_b1 [G4];
__device__ __half g_h1a[BATCH*HID];     // layer1 h ping-pong
__device__ __half g_h1b[BATCH*HID];
__device__ __half g_hz [BATCH*HID];     // zero h
__device__ float g_h1f [BATCH*HID];     // layer1 final h fp32
__device__ unsigned g_flags[2*128*8];   // tree-barrier arrival flags
__device__ unsigned g_go[2*8];          // tree-barrier go words

// ---------------------------------------------------------------------------
// Prep kernels
// ---------------------------------------------------------------------------
struct WcvtArgs {
    const float* src[16];
    __half* dst[16];
    int K[16];
    int g[16];
};

// W[K][1024](fp32, col u) -> dst[4u+g][K] fp16; one launch for all 16 mats.
__global__ void wcvt_all(WcvtArgs a)
{
    __shared__ float s[32][33];
    const int z = blockIdx.z;
    const int K = a.K[z];
    const int k0 = blockIdx.x * 32;
    if (k0 >= K) return;
    const float* W = a.src[z];
    __half* B = a.dst[z];
    const int g = a.g[z];
    const int u0 = blockIdx.y * 32;
    const int tx = threadIdx.x, ty = threadIdx.y;        // (32, 8)
#pragma unroll
    for (int j = 0; j < 4; j++)
        s[ty + j*8][tx] = W[(size_t)(k0 + ty + j*8) * HID + u0 + tx];
    __syncthreads();
#pragma unroll
    for (int j = 0; j < 4; j++) {
        int uu = ty + j*8;
        B[(size_t)(4*(u0 + uu) + g) * K + k0 + tx] = __float2half(s[tx][uu]);
    }
}

__global__ void pack_b4(const float* __restrict__ a, const float* __restrict__ b,
                        const float* __restrict__ c, const float* __restrict__ d,
                        float4* __restrict__ dst)
{
    int u = blockIdx.x * blockDim.x + threadIdx.x;
    if (u < HID) dst[u] = make_float4(a[u], b[u], c[u], d[u]);
}

__global__ void zero_init(__half* __restrict__ hz,
                          unsigned* __restrict__ flags,
                          unsigned* __restrict__ go)
{
    int idx = blockIdx.x * blockDim.x + threadIdx.x;
    if (idx < BATCH * HID) hz[idx] = __float2half(0.f);
    if (idx < 2*128*8) flags[idx] = 0;
    if (idx < 2*8) go[idx] = 0;
}

__global__ void embed_f16(const int* __restrict__ X, const float* __restrict__ C,
                          __half* __restrict__ E)
{
    int idx = blockIdx.x * blockDim.x + threadIdx.x;
    if (idx < ROWS * EMB) {
        int row = idx >> 9, e = idx & 511;
        int t = row >> 6, b = row & 63;
        int tok = X[b * SEQ + t];
        E[idx] = __float2half(C[(size_t)tok * EMB + e]);
    }
}

// ---------------------------------------------------------------------------
// HMMA fp16 GEMM with 2-stage cp.async pipeline:
// C[M][4096] = A[M][K] @ B[4096][K]^T, 128x64 tile, 256 thr.
// Stage: [0,10240) A (128 rows x 80B), [10240,15360) B (64 rows x 80B).
// ---------------------------------------------------------------------------
#define MM_STAGE 15360
#define MM_SMEM  (2*MM_STAGE)
__global__ __launch_bounds__(256)
void mm_mma(const __half* __restrict__ Ag, const __half* __restrict__ Bg,
            float* __restrict__ Cm, int K)
{
    extern __shared__ __align__(16) char smc[];
    const int tid = threadIdx.x, lane = tid & 31, w = tid >> 5;
    const int m0 = blockIdx.y * 128, n0 = blockIdx.x * 64;
    const int wm = (w & 3) * 32, wn = (w >> 2) * 32;
    const int g = lane >> 2, tig = lane & 3;
    const int sub = lane >> 3, lr = lane & 7;
    const uint32_t sbase = smem_u32(smc);

    float acc[2][4][4];
#pragma unroll
    for (int ti = 0; ti < 2; ti++)
#pragma unroll
        for (int j = 0; j < 4; j++)
#pragma unroll
            for (int q = 0; q < 4; q++) acc[ti][j][q] = 0.f;

    uint32_t aOff[2];   // [mtile], relative to stage base
#pragma unroll
    for (int ti = 0; ti < 2; ti++)
        aOff[ti] = (wm + ti*16 + (sub & 1)*8 + lr)*80 + (sub >> 1)*16;

    const int ar = tid >> 2, as4 = tid & 3;

    auto issue = [&](int c) {
        uint32_t base = sbase + (c & 1) * MM_STAGE;
        size_t kb = (size_t)c * 32;
#pragma unroll
        for (int i = 0; i < 2; i++) {
            int r = ar + i * 64;
            cpa16(base + r*80 + as4*16, Ag + (size_t)(m0 + r) * K + kb + as4*8);
        }
        cpa16(base + 10240 + ar*80 + as4*16,
              Bg + (size_t)(n0 + ar) * K + kb + as4*8);
        cpa_commit();
    };

    issue(0);
    const int nchunk = K >> 5;
    for (int c = 0; c < nchunk; c++) {
        __syncthreads();                 // stage (c+1)&1 free for refill
        if (c + 1 < nchunk) { issue(c + 1); cpa_wait<1>(); }
        else                { cpa_wait<0>(); }
        __syncthreads();                 // cp.async data visible to all

        const uint32_t st = sbase + (c & 1) * MM_STAGE;
        const uint32_t stRel = (c & 1) * MM_STAGE;
#pragma unroll
        for (int ks = 0; ks < 2; ks++) {
            uint32_t a[2][4];
#pragma unroll
            for (int ti = 0; ti < 2; ti++)
                ldmatrix_x4(a[ti], st + aOff[ti] + ks*32);
            uint32_t bh[4][2];
#pragma unroll
            for (int j = 0; j < 4; j++) {
                uint32_t off = stRel + 10240 + (wn + 8*j + g)*80 + ks*32 + tig*4;
                bh[j][0] = *(const uint32_t*)(smc + off);
                bh[j][1] = *(const uint32_t*)(smc + off + 16);
            }
#pragma unroll
            for (int ti = 0; ti < 2; ti++)
#pragma unroll
                for (int j = 0; j < 4; j++)
                    mma16816(acc[ti][j], a[ti], bh[j]);
        }
    }

#pragma unroll
    for (int ti = 0; ti < 2; ti++) {
        int row = m0 + wm + ti*16 + g;
#pragma unroll
        for (int j = 0; j < 4; j++) {
            int col = n0 + wn + 8*j + tig*2;
            *(float2*)&Cm[(size_t)row * G4 + col] =
                make_float2(acc[ti][j][0], acc[ti][j][1]);
            *(float2*)&Cm[(size_t)(row + 8) * G4 + col] =
                make_float2(acc[ti][j][2], acc[ti][j][3]);
        }
    }
}

// ---------------------------------------------------------------------------
// Persistent LSTM recurrence kernel (fp16, whole-h in smem).
// 128 blocks x 256 thr. Block owns 32 gate columns; weight slice (32x1024
// fp16 = 66KB) + TWO h-halves (64x512 fp16 = 65KB each) in smem.
// Per step: issue half0, sync, compute half0 while half1 streams, sync,
// compute half1 -> only 2 syncthreads of pipeline overhead per step.
// ---------------------------------------------------------------------------
#define PW 2064                       // weight smem row pitch (2048 + 16 pad)
#define PAH 1040                      // A-half row pitch (1024 + 16 pad)
#define W_BYTES (32*PW)               // 66048
#define A_HALF (64*PAH)               // 66560
#define A_OFF   W_BYTES
#define SM_PERSIST (A_OFF + 2*A_HALF) // 199168

__global__ __launch_bounds__(256, 1)
void lstm_persist(const __half* __restrict__ Wg,
                  const float* __restrict__ XG, const float* __restrict__ bias,
                  const __half* __restrict__ hz,
                  __half* __restrict__ HA, __half* __restrict__ HB,
                  float* __restrict__ hf,
                  unsigned* __restrict__ flags, unsigned* __restrict__ go, int mode)
{
    extern __shared__ __align__(16) char sm[];
    char* sW = sm;
    const uint32_t aAbs = smem_u32(sm) + A_OFF;

    const int tid = threadIdx.x, lane = tid & 31, w = tid >> 5;
    const int wr = w & 3, wc = w >> 2;
    const int g = lane >> 2, tig = lane & 3;
    const int sub = lane >> 3, lr = lane & 7;
    const int n0 = blockIdx.x * 32;

    // ---- load this block's weight slice into smem (once) ----
    for (int idx = tid; idx < 4096; idx += 256) {
        int r = idx >> 7, s = idx & 127;
        *(uint4*)(sW + r*PW + s*16) =
            *(const uint4*)(Wg + ((size_t)(n0 + r) << 10) + s*8);
    }
    __syncthreads();

    const uint32_t rowoff = (16*wr + (sub & 1)*8 + lr)*PAH + (sub >> 1)*16;
    const int brow0 = (wc*16 + g)*PW;
    const int brow1 = (wc*16 + 8 + g)*PW;
    const int m1 = 16*wr + g, m2 = m1 + 8;
    const int Jc0 = n0 + wc*16 + tig*2;
    const int Jc1 = Jc0 + 8;
    const float2 bb0 = *(const float2*)&bias[Jc0];
    const float2 bb1 = *(const float2*)&bias[Jc1];
    const bool co = (tig & 1);
    const int u0 = Jc0 >> 2, u1 = Jc1 >> 2;

    // cp.async mapping for one 64x512 half: 16 x uint4 per thread
    const int iar = tid >> 2;            // not used; see issue()

    float cc00 = 0.f, cc01 = 0.f, cc10 = 0.f, cc11 = 0.f;

    for (int t = 0; t < SEQ; t++) {
        const __half* ph;
        __half* dh;
        if (mode == 0) {
            dh = HA + (size_t)t * BATCH * HID;
            ph = t ? dh - BATCH*HID : hz;
        } else {
            if (t & 1) { dh = HB; ph = HA; }
            else       { dh = HA; ph = t ? HB : hz; }
        }

        // prefetch xg for this step (independent of the recurrence chain)
        const float* xb = XG + (((size_t)(t*64)) << 12);
        const float2 x1_0 = *(const float2*)(xb + (size_t)m1*G4 + Jc0);
        const float2 x2_0 = *(const float2*)(xb + (size_t)m2*G4 + Jc0);
        const float2 x1_1 = *(const float2*)(xb + (size_t)m1*G4 + Jc1);
        const float2 x2_1 = *(const float2*)(xb + (size_t)m2*G4 + Jc1);

        // issue one 64x512 half (64 KB) of h_prev into smem buffer `half`
        auto issue = [&](int half) {
            uint32_t dst = aAbs + half * A_HALF;
            const __half* src = ph + half * 512;
#pragma unroll
            for (int i = 0; i < 16; i++) {
                int lin = tid + i * 256;
                int r = lin >> 6, s = lin & 63;
                cpa16(dst + r*PAH + s*16, src + ((size_t)r << 10) + s*8);
            }
            cpa_commit();
        };

        issue(0);
        issue(1);

        float acc0[4] = {0.f, 0.f, 0.f, 0.f};
        float acc1[4] = {0.f, 0.f, 0.f, 0.f};

#pragma unroll
        for (int half = 0; half < 2; half++) {
            if (half == 0) cpa_wait<1>(); else cpa_wait<0>();
            __syncthreads();
            const uint32_t ah = aAbs + half * A_HALF + rowoff;
            const int kbase = half * 1024;     // byte offset into weight row
#pragma unroll 8
            for (int ks = 0; ks < 32; ks++) {
                uint32_t a0[4];
                ldmatrix_x4(a0, ah + ks*32);
                const int ko = kbase + ks*32 + tig*4;
                uint32_t b0[2], b1[2];
                b0[0] = *(const uint32_t*)(sW + brow0 + ko);
                b0[1] = *(const uint32_t*)(sW + brow0 + ko + 16);
                b1[0] = *(const uint32_t*)(sW + brow1 + ko);
                b1[1] = *(const uint32_t*)(sW + brow1 + ko + 16);
                mma16816(acc0, a0, b0);
                mma16816(acc1, a0, b1);
            }
        }

        // ---- pointwise epilogue ----
        {
            float p0 = acc0[0] + x1_0.x + bb0.x;
            float p1 = acc0[1] + x1_0.y + bb0.y;
            float p2 = acc0[2] + x2_0.x + bb0.x;
            float p3 = acc0[3] + x2_0.y + bb0.y;
            float a0v = co ? tanhf(p0) : sigf(p0);
            float a1v = sigf(p1);
            float a2v = co ? tanhf(p2) : sigf(p2);
            float a3v = sigf(p3);
            float C1 = __shfl_xor_sync(0xFFFFFFFFu, a0v, 1);
            float O1 = __shfl_xor_sync(0xFFFFFFFFu, a1v, 1);
            float C2 = __shfl_xor_sync(0xFFFFFFFFu, a2v, 1);
            float O2 = __shfl_xor_sync(0xFFFFFFFFu, a3v, 1);
            if (!co) {
                cc00 = a0v * cc00 + a1v * C1;
                float hv = O1 * tanhf(cc00);
                dh[m1*HID + u0] = __float2half(hv);
                if (hf && t == SEQ-1) hf[m1*HID + u0] = hv;
                cc01 = a2v * cc01 + a3v * C2;
                hv = O2 * tanhf(cc01);
                dh[m2*HID + u0] = __float2half(hv);
                if (hf && t == SEQ-1) hf[m2*HID + u0] = hv;
            }
        }
        {
            float p0 = acc1[0] + x1_1.x + bb1.x;
            float p1 = acc1[1] + x1_1.y + bb1.y;
            float p2 = acc1[2] + x2_1.x + bb1.x;
            float p3 = acc1[3] + x2_1.y + bb1.y;
            float a0v = co ? tanhf(p0) : sigf(p0);
            float a1v = sigf(p1);
            float a2v = co ? tanhf(p2) : sigf(p2);
            float a3v = sigf(p3);
            float C1 = __shfl_xor_sync(0xFFFFFFFFu, a0v, 1);
            float O1 = __shfl_xor_sync(0xFFFFFFFFu, a1v, 1);
            float C2 = __shfl_xor_sync(0xFFFFFFFFu, a2v, 1);
            float O2 = __shfl_xor_sync(0xFFFFFFFFu, a3v, 1);
            if (!co) {
                cc10 = a0v * cc10 + a1v * C1;
                float hv = O1 * tanhf(cc10);
                dh[m1*HID + u1] = __float2half(hv);
                if (hf && t == SEQ-1) hf[m1*HID + u1] = hv;
                cc11 = a2v * cc11 + a3v * C2;
                hv = O2 * tanhf(cc11);
                dh[m2*HID + u1] = __float2half(hv);
                if (hf && t == SEQ-1) hf[m2*HID + u1] = hv;
            }
        }

        // ---- two-level tree grid barrier (skip after last step) ----
        if (t != SEQ-1) {
            const unsigned sense = (unsigned)(t + 1);
            __syncthreads();                      // all h stores done, block-wide
            if (blockIdx.x == 0) {
                if (tid >= 1 && tid < 128) {
                    const unsigned* f = flags + tid*8;
                    while (ld_acquire(f) < sense) {}
                }
                __syncthreads();
                if (tid == 0) st_release(go, sense);
            } else {
                if (tid == 0) {
                    st_release(flags + blockIdx.x*8, sense);
                    while (ld_acquire(go) < sense) {}
                }
                __syncthreads();
            }
        }
    }
    (void)iar;
}

// ---------------------------------------------------------------------------
// Output projection: out[64][N] = A[64][K] @ B[K][N] + bias (fp32)
// ---------------------------------------------------------------------------
__global__ __launch_bounds__(256)
void sgemm_out(const float* __restrict__ A, const float* __restrict__ B,
               float* __restrict__ Cmat, int N, int K, const float* __restrict__ bias)
{
    __shared__ __align__(16) float As[16][68];
    __shared__ __align__(16) float Bs[16][68];

    const int tid = threadIdx.x;
    const int tx = tid & 15, ty = tid >> 4;
    const int n0 = blockIdx.x * 64;

    float acc[4][4];
#pragma unroll
    for (int r = 0; r < 4; r++)
#pragma unroll
        for (int c = 0; c < 4; c++) acc[r][c] = 0.f;

    const int am = tid >> 2;
    const int akg = tid & 3;
    const int bk = tid >> 4;
    const int bn4 = tid & 15;

    for (int k0 = 0; k0 < K; k0 += 16) {
        float4 av = *(const float4*)&A[(size_t)am * K + k0 + akg * 4];
        float4 bv;
        if (n0 + bn4 * 4 < N)
            bv = *(const float4*)&B[(size_t)(k0 + bk) * N + n0 + bn4 * 4];
        else
            bv = make_float4(0.f, 0.f, 0.f, 0.f);
        As[akg*4 + 0][am] = av.x;
        As[akg*4 + 1][am] = av.y;
        As[akg*4 + 2][am] = av.z;
        As[akg*4 + 3][am] = av.w;
        *(float4*)&Bs[bk][bn4 * 4] = bv;
        __syncthreads();
#pragma unroll
        for (int kk = 0; kk < 16; kk++) {
            float4 a4 = *(const float4*)&As[kk][ty * 4];
            float4 b4 = *(const float4*)&Bs[kk][tx * 4];
            acc[0][0] = fmaf(a4.x, b4.x, acc[0][0]);
            acc[0][1] = fmaf(a4.x, b4.y, acc[0][1]);
            acc[0][2] = fmaf(a4.x, b4.z, acc[0][2]);
            acc[0][3] = fmaf(a4.x, b4.w, acc[0][3]);
            acc[1][0] = fmaf(a4.y, b4.x, acc[1][0]);
            acc[1][1] = fmaf(a4.y, b4.y, acc[1][1]);
            acc[1][2] = fmaf(a4.y, b4.z, acc[1][2]);
            acc[1][3] = fmaf(a4.y, b4.w, acc[1][3]);
            acc[2][0] = fmaf(a4.z, b4.x, acc[2][0]);
            acc[2][1] = fmaf(a4.z, b4.y, acc[2][1]);
            acc[2][2] = fmaf(a4.z, b4.z, acc[2][2]);
            acc[2][3] = fmaf(a4.z, b4.w, acc[2][3]);
            acc[3][0] = fmaf(a4.w, b4.x, acc[3][0]);
            acc[3][1] = fmaf(a4.w, b4.y, acc[3][1]);
            acc[3][2] = fmaf(a4.w, b4.z, acc[3][2]);
            acc[3][3] = fmaf(a4.w, b4.w, acc[3][3]);
        }
        __syncthreads();
    }

#pragma unroll
    for (int r = 0; r < 4; r++) {
        int m = ty * 4 + r;
#pragma unroll
        for (int c = 0; c < 4; c++) {
            int n = n0 + tx * 4 + c;
            if (n < N) Cmat[(size_t)m * N + n] = acc[r][c] + bias[n];
        }
    }
}

// ---------------------------------------------------------------------------
// Host launcher (graph-capturable: kernel launches only)
// ---------------------------------------------------------------------------
extern "C" void kernel_launch(void* const* d_in, const int* in_sizes, int n_in,
                              void* d_out, int out_size)
{
    const int*   X     = (const int*)  d_in[0];
    const float* Cemb  = (const float*)d_in[1];
    const float* W_fx  = (const float*)d_in[2];
    const float* W_fh  = (const float*)d_in[3];
    const float* W_ix  = (const float*)d_in[4];
    const float* W_ih  = (const float*)d_in[5];
    const float* W_Cx  = (const float*)d_in[6];
    const float* W_Ch  = (const float*)d_in[7];
    const float* W_ox  = (const float*)d_in[8];
    const float* W_oh  = (const float*)d_in[9];
    const float* W_fx1 = (const float*)d_in[10];
    const float* W_fh1 = (const float*)d_in[11];
    const float* W_ix1 = (const float*)d_in[12];
    const float* W_ih1 = (const float*)d_in[13];   // unused (reference bug kept)
    const float* W_Cx1 = (const float*)d_in[14];
    const float* W_Ch1 = (const float*)d_in[15];
    const float* W_ox1 = (const float*)d_in[16];
    const float* W_oh1 = (const float*)d_in[17];
    const float* W_out = (const float*)d_in[18];
    const float* b_f   = (const float*)d_in[19];
    const float* b_i   = (const float*)d_in[20];
    const float* b_C   = (const float*)d_in[21];
    const float* b_o   = (const float*)d_in[22];
    const float* b_f1  = (const float*)d_in[23];
    const float* b_i1  = (const float*)d_in[24];
    const float* b_C1  = (const float*)d_in[25];
    const float* b_o1  = (const float*)d_in[26];
    const float* b_out = (const float*)d_in[27];
    float* out = (float*)d_out;
    (void)W_ih1; (void)n_in; (void)in_sizes; (void)out_size;

    __half *E, *H, *B0, *B1, *R0, *R1, *h1a, *h1b, *hz;
    float *XG0, *XG1, *b0, *b1, *h1f;
    unsigned *flags, *go;
    cudaGetSymbolAddress((void**)&E,  g_E);
    cudaGetSymbolAddress((void**)&H,  g_H);
    cudaGetSymbolAddress((void**)&B0, g_B0);
    cudaGetSymbolAddress((void**)&B1, g_B1);
    cudaGetSymbolAddress((void**)&R0, g_R0);
    cudaGetSymbolAddress((void**)&R1, g_R1);
    cudaGetSymbolAddress((void**)&XG0, g_XG0);
    cudaGetSymbolAddress((void**)&XG1, g_XG1);
    cudaGetSymbolAddress((void**)&b0, g_b0);
    cudaGetSymbolAddress((void**)&b1, g_b1);
    cudaGetSymbolAddress((void**)&h1a, g_h1a);
    cudaGetSymbolAddress((void**)&h1b, g_h1b);
    cudaGetSymbolAddress((void**)&hz,  g_hz);
    cudaGetSymbolAddress((void**)&h1f, g_h1f);
    cudaGetSymbolAddress((void**)&flags, g_flags);
    cudaGetSymbolAddress((void**)&go,   g_go);

    cudaFuncSetAttribute(lstm_persist,
                         cudaFuncAttributeMaxDynamicSharedMemorySize, SM_PERSIST);
    cudaFuncSetAttribute(mm_mma,
                         cudaFuncAttributeMaxDynamicSharedMemorySize, MM_SMEM);

    // All 16 weight conversions in one launch
    WcvtArgs wa;
    const float* srcs[16] = {W_fx, W_ix, W_Cx, W_ox,
                             W_fx1, W_ix1, W_Cx1, W_ox1,
                             W_fh,  W_ih,  W_Ch,  W_oh,
                             W_fh1, W_ih,  W_Ch1, W_oh1};  // layer1 i-gate = W_ih (ref bug)
    for (int z = 0; z < 16; z++) {
        wa.src[z] = srcs[z];
        wa.g[z] = z & 3;
        if (z < 4)       { wa.dst[z] = B0; wa.K[z] = EMB; }
        else if (z < 8)  { wa.dst[z] = B1; wa.K[z] = HID; }
        else if (z < 12) { wa.dst[z] = R0; wa.K[z] = HID; }
        else             { wa.dst[z] = R1; wa.K[z] = HID; }
    }
    wcvt_all<<<dim3(32, 32, 16), dim3(32, 8)>>>(wa);

    pack_b4<<<(HID + 255)/256, 256>>>(b_f,  b_i,  b_C,  b_o,  (float4*)b0);
    pack_b4<<<(HID + 255)/256, 256>>>(b_f1, b_i1, b_C1, b_o1, (float4*)b1);

    zero_init<<<(BATCH*HID + 255)/256, 256>>>(hz, flags, go);
    embed_f16<<<(ROWS*EMB + 255)/256, 256>>>(X, Cemb, E);

    // XG0 = E @ Wx0 (fp16 HMMA, pipelined)
    mm_mma<<<dim3(G4/64, ROWS/128), 256, MM_SMEM>>>(E, B0, XG0, EMB);

    // Layer 0 recurrence: persistent, 128 grid-synced steps
    lstm_persist<<<128, 256, SM_PERSIST>>>(R0, XG0, b0, hz,
                                           H, nullptr, nullptr,
                                           flags, go, 0);

    // XG1 = H @ Wx1 (fp16 HMMA, pipelined)
    mm_mma<<<dim3(G4/64, ROWS/128), 256, MM_SMEM>>>(H, B1, XG1, HID);

    // Layer 1 recurrence: persistent, ping-pong h buffers
    lstm_persist<<<128, 256, SM_PERSIST>>>(R1, XG1, b1, hz,
                                           h1a, h1b, h1f,
                                           flags + 128*8, go + 8, 1);

    // out = h1 @ W_out + b_out
    sgemm_out<<<dim3((N_CLASS + 63)/64, 1), 256>>>(h1f, W_out, out,
                                                   N_CLASS, HID, b_out);
}